// round 5
// baseline (speedup 1.0000x reference)
#include <cuda_runtime.h>
#include <cuda_fp16.h>
#include <math.h>

#define B_ 8
#define N_ 4096
#define D_ 1024
#define H_ 8
#define NTOK 4097   // 1 cls + 4096 feat tokens

// ---------------- scratch (static device allocations only) ----------------
__device__ unsigned long long g_best[B_];     // packed (score_key << 32) | ~idx
__device__ float  g_Q[B_*D_];
__device__ float  g_Qp[B_*D_];
__device__ float  g_u[B_*H_*D_];
__device__ __half g_x[(size_t)B_*N_*D_];      // post relu+conv features, fp16 storage
__device__ float  g_logits[B_*H_*NTOK];       // logits -> softmax in place
__device__ float  g_xbar[B_*H_*D_];
__device__ float  g_O[B_*D_];
__device__ float  g_O2[B_*D_];

__device__ __forceinline__ float warp_sum(float v){
    #pragma unroll
    for (int o = 16; o; o >>= 1) v += __shfl_xor_sync(0xffffffffu, v, o);
    return v;
}

__device__ __forceinline__ void h8_to_f(uint4 v, float* f){
    __half2 h0 = *reinterpret_cast<__half2*>(&v.x);
    __half2 h1 = *reinterpret_cast<__half2*>(&v.y);
    __half2 h2 = *reinterpret_cast<__half2*>(&v.z);
    __half2 h3 = *reinterpret_cast<__half2*>(&v.w);
    float2 a = __half22float2(h0); f[0]=a.x; f[1]=a.y;
    float2 b = __half22float2(h1); f[2]=b.x; f[3]=b.y;
    float2 c = __half22float2(h2); f[4]=c.x; f[5]=c.y;
    float2 d = __half22float2(h3); f[6]=d.x; f[7]=d.y;
}

// ---------------- 0) zero g_u (accumulated atomically each run) ----------------
__global__ void k_init(){
    int id = blockIdx.x*256 + threadIdx.x;
    ((float4*)g_u)[id] = make_float4(0.f,0.f,0.f,0.f);
}

// ---------------- 1) score + fused argmax: per-block packed atomicMax ----------------
__global__ void k_score(const float* __restrict__ inp, const float* __restrict__ wenc){
    int gw   = blockIdx.x*8 + (threadIdx.x >> 5);    // row id, 0..B*N-1 (same b within block)
    int lane = threadIdx.x & 31;
    const float4* row = (const float4*)(inp + (size_t)gw * D_);
    const float4* wp  = (const float4*)wenc;
    float acc = 0.f;
    #pragma unroll
    for (int j = 0; j < 8; j++){
        float4 x = row[j*32 + lane];
        float4 w = __ldg(&wp[j*32 + lane]);
        acc += x.x*w.x + x.y*w.y + x.z*w.z + x.w*w.w;
    }
    acc = warp_sum(acc);
    __shared__ unsigned long long sbest[8];
    if (lane == 0){
        unsigned int fb  = __float_as_uint(acc);
        unsigned int key = (fb & 0x80000000u) ? ~fb : (fb | 0x80000000u);
        unsigned int n   = (unsigned int)(gw & (N_-1));
        sbest[threadIdx.x >> 5] = ((unsigned long long)key << 32) | (unsigned long long)(~n);
    }
    __syncthreads();
    if (threadIdx.x == 0){
        unsigned long long m = sbest[0];
        #pragma unroll
        for (int i = 1; i < 8; i++) m = (sbest[i] > m) ? sbest[i] : m;
        atomicMax(&g_best[gw >> 12], m);
    }
}

// ---------------- 2) extract idx, copy Q row ----------------
__global__ void k_prep(const float* __restrict__ inp){
    int b = blockIdx.x;
    unsigned int n = (~(unsigned int)(g_best[b] & 0xffffffffull)) & (N_-1);
    const float* src = inp + ((size_t)b*N_ + n) * D_;
    for (int d = threadIdx.x; d < D_; d += 256) g_Q[b*D_ + d] = src[d];
}

// ---------------- 3) Qp: block per output row j ----------------
__global__ void __launch_bounds__(256) k_qp(const float* __restrict__ Wq, const float* __restrict__ bq){
    int j = blockIdx.x, t = threadIdx.x, lane = t & 31, wp = t >> 5;
    float4 w = __ldg((const float4*)(Wq + (size_t)j * D_) + t);
    float acc[B_];
    #pragma unroll
    for (int b = 0; b < B_; b++){
        float4 q = __ldg((const float4*)(g_Q + b*D_) + t);
        acc[b] = w.x*q.x + w.y*q.y + w.z*q.z + w.w*q.w;
    }
    __shared__ float red[8][B_];
    #pragma unroll
    for (int b = 0; b < B_; b++) acc[b] = warp_sum(acc[b]);
    if (lane == 0){
        #pragma unroll
        for (int b = 0; b < B_; b++) red[wp][b] = acc[b];
    }
    __syncthreads();
    if (t < B_){
        float s = 0.f;
        #pragma unroll
        for (int i = 0; i < 8; i++) s += red[i][t];
        g_Qp[t*D_ + j] = s + bq[j];
    }
}

// ---------------- 4) u[b,h,i] += partial (grid (16,H,4), atomic accumulate) ----------------
__global__ void __launch_bounds__(256) k_u(const float* __restrict__ Wk){
    int h  = blockIdx.y, jc = blockIdx.z;
    int il = threadIdx.x & 63;
    int js = threadIdx.x >> 6;

    __shared__ float qp[B_][32];
    { int t = threadIdx.x;
      qp[t >> 5][t & 31] = g_Qp[(t >> 5)*D_ + h*128 + jc*32 + (t & 31)]; }
    __syncthreads();

    int i = blockIdx.x*64 + il;
    const float* wkp = Wk + (size_t)(h*128 + jc*32 + js*8) * D_ + i;
    float acc[B_];
    #pragma unroll
    for (int b = 0; b < B_; b++) acc[b] = 0.f;
    #pragma unroll
    for (int j = 0; j < 8; j++){
        float w = wkp[(size_t)j * D_];
        #pragma unroll
        for (int b = 0; b < B_; b++) acc[b] += qp[b][js*8 + j] * w;
    }

    __shared__ float part[4][64][B_];
    #pragma unroll
    for (int b = 0; b < B_; b++) part[js][il][b] = acc[b];
    __syncthreads();

    for (int idx = threadIdx.x; idx < 64*B_; idx += 256){
        int ii = idx >> 3, b = idx & 7;
        float s = part[0][ii][b] + part[1][ii][b] + part[2][ii][b] + part[3][ii][b];
        atomicAdd(&g_u[((size_t)(b*H_ + h))*D_ + blockIdx.x*64 + ii], s);
    }
}

// ---------------- 5) relu + depthwise 3x3 conv (SAME) + residual -> g_x (fp16) ----------------
// 2 channels/thread (float2): ~60 regs -> 4 blocks/SM. Block = 32 ch-groups x 8 rows,
// full 64-w register slide. Grid (16, 8, B).
__global__ void __launch_bounds__(256, 4) k_conv(const float* __restrict__ inp,
                                                 const float* __restrict__ convw,
                                                 const float* __restrict__ convb){
    int b  = blockIdx.z;
    int cg = threadIdx.x & 31;
    int hr = threadIdx.x >> 5;
    int c0 = blockIdx.x*64 + cg*2;
    int h  = blockIdx.y*8 + hr;

    const float* base = inp + (size_t)b*N_*D_ + c0;
    float2 qv = *(const float2*)(g_Q + b*D_ + c0);
    float2 cb = *(const float2*)(convb + c0);

    float2 wgt[9];
    #pragma unroll
    for (int k = 0; k < 9; k++){
        wgt[k].x = convw[(c0+0)*9 + k];
        wgt[k].y = convw[(c0+1)*9 + k];
    }

    bool vld[3];
    const float* rp[3];
    #pragma unroll
    for (int r = 0; r < 3; r++){
        int hh = h - 1 + r;
        vld[r] = (hh >= 0) && (hh < 64);
        int hc = hh < 0 ? 0 : (hh > 63 ? 63 : hh);
        rp[r] = base + (size_t)(hc*64) * D_;
    }

    const float2 z2 = make_float2(0.f, 0.f);
    float2 L[3], C[3], R[3];
    #pragma unroll
    for (int r = 0; r < 3; r++){
        L[r] = z2;
        if (vld[r]){
            float2 v = *(const float2*)(rp[r]);
            C[r] = make_float2(fmaxf(v.x - qv.x, 0.f), fmaxf(v.y - qv.y, 0.f));
        } else C[r] = z2;
    }

    __half* outbase = g_x + ((size_t)b*N_ + h*64) * D_ + c0;
    for (int w = 0; w < 64; w++){
        #pragma unroll
        for (int r = 0; r < 3; r++){
            if (w < 63 && vld[r]){
                float2 v = *(const float2*)(rp[r] + (size_t)(w + 1) * D_);
                R[r] = make_float2(fmaxf(v.x - qv.x, 0.f), fmaxf(v.y - qv.y, 0.f));
            } else R[r] = z2;
        }
        float2 acc = cb;
        #pragma unroll
        for (int r = 0; r < 3; r++){
            acc.x += wgt[r*3+0].x*L[r].x + wgt[r*3+1].x*C[r].x + wgt[r*3+2].x*R[r].x;
            acc.y += wgt[r*3+0].y*L[r].y + wgt[r*3+1].y*C[r].y + wgt[r*3+2].y*R[r].y;
        }
        __half2 hv = __floats2half2_rn(C[1].x + acc.x, C[1].y + acc.y);
        *(__half2*)(outbase + (size_t)w * D_) = hv;
        #pragma unroll
        for (int r = 0; r < 3; r++){ L[r] = C[r]; C[r] = R[r]; }
    }
}

// ---------------- 6) logits[b,h,k] = (u[b,h].x_k)/32  (u staged in shared; cb cancels) ----
__global__ void __launch_bounds__(256) k_logits(){
    int b    = blockIdx.y;
    int warp = threadIdx.x >> 5, lane = threadIdx.x & 31;
    int t0   = blockIdx.x*32 + warp*4;

    __shared__ float4 us[2048];           // u[b]: 8 heads x 1024 f32 = 32KB
    {
        const float4* up = (const float4*)(g_u + (size_t)b*H_*D_);
        for (int r = threadIdx.x; r < 2048; r += 256) us[r] = up[r];
    }
    __syncthreads();

    const __half* xbase = g_x + ((size_t)b*N_ + t0) * D_;
    float acc[4][8];
    #pragma unroll
    for (int t = 0; t < 4; t++)
        #pragma unroll
        for (int hh = 0; hh < 8; hh++) acc[t][hh] = 0.f;

    #pragma unroll
    for (int it = 0; it < 4; it++){
        int ck = it*32 + lane;
        float xf[4][8];
        #pragma unroll
        for (int t = 0; t < 4; t++){
            uint4 raw = *(const uint4*)(xbase + (size_t)t*D_ + ck*8);
            h8_to_f(raw, xf[t]);
        }
        #pragma unroll
        for (int hh = 0; hh < 8; hh++){
            float4 u0 = us[hh*256 + ck*2 + 0];
            float4 u1 = us[hh*256 + ck*2 + 1];
            #pragma unroll
            for (int t = 0; t < 4; t++){
                acc[t][hh] += xf[t][0]*u0.x + xf[t][1]*u0.y + xf[t][2]*u0.z + xf[t][3]*u0.w
                            + xf[t][4]*u1.x + xf[t][5]*u1.y + xf[t][6]*u1.z + xf[t][7]*u1.w;
            }
        }
    }
    #pragma unroll
    for (int t = 0; t < 4; t++)
        #pragma unroll
        for (int hh = 0; hh < 8; hh++) acc[t][hh] = warp_sum(acc[t][hh]);

    if (lane < 8){
        #pragma unroll
        for (int t = 0; t < 4; t++)
            g_logits[((size_t)(b*H_ + lane))*NTOK + t0 + t + 1] = acc[t][lane] * 0.03125f;
    }
}

// ---------------- 7) softmax over 4097 (cls logit computed inline) + init xbar ----------------
__global__ void __launch_bounds__(256) k_softmax(const float* __restrict__ cls){
    int bh = blockIdx.x;
    float* lg = g_logits + (size_t)bh * NTOK;
    __shared__ float sred[8];
    __shared__ float sbc;
    int lane = threadIdx.x & 31, warp = threadIdx.x >> 5;

    // cls logit (k=0): dot(u[bh], cls)/32
    {
        const float* u = g_u + (size_t)bh * D_;
        float a = 0.f;
        for (int d = threadIdx.x; d < D_; d += 256) a += u[d] * cls[d];
        a = warp_sum(a);
        if (lane == 0) sred[warp] = a;
        __syncthreads();
        if (threadIdx.x == 0){
            float s = 0.f;
            #pragma unroll
            for (int i = 0; i < 8; i++) s += sred[i];
            lg[0] = s * 0.03125f;
        }
        __syncthreads();
    }

    float mx = -INFINITY;
    for (int k = threadIdx.x; k < NTOK; k += 256) mx = fmaxf(mx, lg[k]);
    #pragma unroll
    for (int o = 16; o; o >>= 1) mx = fmaxf(mx, __shfl_xor_sync(0xffffffffu, mx, o));
    if (lane == 0) sred[warp] = mx;
    __syncthreads();
    if (threadIdx.x == 0){
        float m = sred[0];
        #pragma unroll
        for (int i = 1; i < 8; i++) m = fmaxf(m, sred[i]);
        sbc = m;
    }
    __syncthreads();
    float m = sbc;

    float sum = 0.f;
    for (int k = threadIdx.x; k < NTOK; k += 256){
        float e = expf(lg[k] - m);
        lg[k] = e;
        sum += e;
    }
    sum = warp_sum(sum);
    if (lane == 0) sred[warp] = sum;
    __syncthreads();
    if (threadIdx.x == 0){
        float s = 0.f;
        #pragma unroll
        for (int i = 0; i < 8; i++) s += sred[i];
        sbc = s;
    }
    __syncthreads();
    float inv = 1.f / sbc;
    for (int k = threadIdx.x; k < NTOK; k += 256) lg[k] *= inv;
    __syncthreads();

    float a0 = lg[0];
    for (int d = threadIdx.x; d < D_; d += 256)
        g_xbar[(size_t)bh * D_ + d] = a0 * cls[d];
}

// ---------------- 8) xbar[b,h,:] += sum_k A[b,h,k] * x_k  (chunk 64, grid 512) ----------------
__global__ void __launch_bounds__(256) k_xbar(){
    int b  = blockIdx.y;
    int k0 = blockIdx.x * 64;
    __shared__ float As[8*64];
    for (int i = threadIdx.x; i < 512; i += 256){
        int hh = i >> 6, kk = i & 63;
        As[i] = g_logits[((size_t)(b*H_ + hh))*NTOK + 1 + k0 + kk];
    }
    __syncthreads();
    const __half* xp = g_x + ((size_t)b*N_ + k0) * D_;
    int d0 = threadIdx.x * 4;
    float4 acc[8];
    #pragma unroll
    for (int hh = 0; hh < 8; hh++) acc[hh] = make_float4(0.f,0.f,0.f,0.f);

    for (int k = 0; k < 64; k++){
        uint2 raw = *(const uint2*)(xp + (size_t)k*D_ + d0);
        __half2 h0 = *reinterpret_cast<__half2*>(&raw.x);
        __half2 h1 = *reinterpret_cast<__half2*>(&raw.y);
        float2 xa = __half22float2(h0);
        float2 xb = __half22float2(h1);
        #pragma unroll
        for (int hh = 0; hh < 8; hh++){
            float a = As[hh*64 + k];
            acc[hh].x += a*xa.x; acc[hh].y += a*xa.y;
            acc[hh].z += a*xb.x; acc[hh].w += a*xb.y;
        }
    }
    #pragma unroll
    for (int hh = 0; hh < 8; hh++){
        float* dst = g_xbar + ((size_t)(b*H_ + hh))*D_ + d0;
        atomicAdd(dst + 0, acc[hh].x);
        atomicAdd(dst + 1, acc[hh].y);
        atomicAdd(dst + 2, acc[hh].z);
        atomicAdd(dst + 3, acc[hh].w);
    }
}

// ---------------- 9) O: block per row j ----------------
__global__ void __launch_bounds__(256) k_O(const float* __restrict__ Wv, const float* __restrict__ bv){
    int j = blockIdx.x, t = threadIdx.x, lane = t & 31, wp = t >> 5;
    int h = j >> 7;
    float4 w = __ldg((const float4*)(Wv + (size_t)j * D_) + t);
    float acc[B_];
    #pragma unroll
    for (int b = 0; b < B_; b++){
        float4 v = __ldg((const float4*)(g_xbar + ((size_t)(b*H_ + h))*D_) + t);
        acc[b] = w.x*v.x + w.y*v.y + w.z*v.z + w.w*v.w;
    }
    __shared__ float red[8][B_];
    #pragma unroll
    for (int b = 0; b < B_; b++) acc[b] = warp_sum(acc[b]);
    if (lane == 0){
        #pragma unroll
        for (int b = 0; b < B_; b++) red[wp][b] = acc[b];
    }
    __syncthreads();
    if (t < B_){
        float s = 0.f;
        #pragma unroll
        for (int i = 0; i < 8; i++) s += red[i][t];
        g_O[t*D_ + j] = g_Qp[t*D_ + j] + bv[j] + s;
    }
}

// ---------------- 10) O2 = O + relu(O @ Wo^T + bo) ----------------
__global__ void __launch_bounds__(256) k_O2(const float* __restrict__ Wo, const float* __restrict__ bo){
    int j = blockIdx.x, t = threadIdx.x, lane = t & 31, wp = t >> 5;
    float4 w = __ldg((const float4*)(Wo + (size_t)j * D_) + t);
    float acc[B_];
    #pragma unroll
    for (int b = 0; b < B_; b++){
        float4 v = __ldg((const float4*)(g_O + (size_t)b*D_) + t);
        acc[b] = w.x*v.x + w.y*v.y + w.z*v.z + w.w*v.w;
    }
    __shared__ float red[8][B_];
    #pragma unroll
    for (int b = 0; b < B_; b++) acc[b] = warp_sum(acc[b]);
    if (lane == 0){
        #pragma unroll
        for (int b = 0; b < B_; b++) red[wp][b] = acc[b];
    }
    __syncthreads();
    if (t < B_){
        float s = 0.f;
        #pragma unroll
        for (int i = 0; i < 8; i++) s += red[i][t];
        g_O2[t*D_ + j] = g_O[t*D_ + j] + fmaxf(s + bo[j], 0.f);
    }
}

// ---------------- 11) out = O2 @ Wfc^T + bfc  -> (8, 2) ----------------
__global__ void k_fc(const float* __restrict__ Wfc, const float* __restrict__ bfc,
                     float* __restrict__ out){
    int b    = blockIdx.x;
    int c    = threadIdx.x >> 5;
    int lane = threadIdx.x & 31;
    const float4* wr = (const float4*)(Wfc + (size_t)c * D_);
    const float4* op = (const float4*)(g_O2 + (size_t)b * D_);
    float acc = 0.f;
    #pragma unroll
    for (int it = 0; it < 8; it++){
        float4 w = wr[it*32 + lane];
        float4 v = op[it*32 + lane];
        acc += w.x*v.x + w.y*v.y + w.z*v.z + w.w*v.w;
    }
    acc = warp_sum(acc);
    if (lane == 0) out[b*2 + c] = acc + bfc[c];
}

// ---------------- stream/event infra (created in global ctor) ----------------
static cudaStream_t s_aux;
static cudaEvent_t  ev_start, ev_q, ev_init, ev_conv;
namespace {
struct _FRMIL_Init {
    _FRMIL_Init(){
        cudaStreamCreateWithFlags(&s_aux, cudaStreamNonBlocking);
        cudaEventCreateWithFlags(&ev_start, cudaEventDisableTiming);
        cudaEventCreateWithFlags(&ev_q,     cudaEventDisableTiming);
        cudaEventCreateWithFlags(&ev_init,  cudaEventDisableTiming);
        cudaEventCreateWithFlags(&ev_conv,  cudaEventDisableTiming);
    }
} _frmil_init_;
}

// ---------------- launcher ----------------
extern "C" void kernel_launch(void* const* d_in, const int* in_sizes, int n_in,
                              void* d_out, int out_size){
    const float* inputs = (const float*)d_in[0];
    const float* Wenc   = (const float*)d_in[1];
    // d_in[2] = b_enc : constant shift through sigmoid, irrelevant for argmax
    const float* cls    = (const float*)d_in[3];
    const float* convw  = (const float*)d_in[4];
    const float* convb  = (const float*)d_in[5];
    const float* Wq     = (const float*)d_in[6];
    const float* bq     = (const float*)d_in[7];
    const float* Wk     = (const float*)d_in[8];
    // d_in[9] = bk : constant per (b,h) logit offset -> cancels in softmax
    const float* Wv     = (const float*)d_in[10];
    const float* bv     = (const float*)d_in[11];
    const float* Wo     = (const float*)d_in[12];
    const float* bo     = (const float*)d_in[13];
    const float* Wfc    = (const float*)d_in[14];
    const float* bfc    = (const float*)d_in[15];
    float* out = (float*)d_out;

    // fork: aux stream zeroes g_u while main streams scores
    cudaEventRecord(ev_start, 0);
    cudaStreamWaitEvent(s_aux, ev_start, 0);
    k_init <<<64, 256, 0, s_aux>>>();
    cudaEventRecord(ev_init, s_aux);

    k_score<<<B_*N_/8, 256>>>(inputs, Wenc);
    k_prep <<<B_, 256>>>(inputs);
    cudaEventRecord(ev_q, 0);

    // aux: conv (the long pole) overlaps qp+u on main
    cudaStreamWaitEvent(s_aux, ev_q, 0);
    k_conv <<<dim3(16, 8, B_), 256, 0, s_aux>>>(inputs, convw, convb);
    cudaEventRecord(ev_conv, s_aux);

    k_qp   <<<D_, 256>>>(Wq, bq);
    cudaStreamWaitEvent(0, ev_init, 0);
    k_u    <<<dim3(16, H_, 4), 256>>>(Wk);

    // join: logits needs conv output + u
    cudaStreamWaitEvent(0, ev_conv, 0);
    k_logits <<<dim3(N_/32, B_), 256>>>();
    k_softmax<<<B_*H_, 256>>>(cls);
    k_xbar   <<<dim3(N_/64, B_), 256>>>();
    k_O      <<<D_, 256>>>(Wv, bv);
    k_O2     <<<D_, 256>>>(Wo, bo);
    k_fc     <<<B_, 64>>>(Wfc, bfc, out);
}

// round 6
// speedup vs baseline: 1.1602x; 1.1602x over previous
#include <cuda_runtime.h>
#include <cuda_fp16.h>
#include <math.h>

#define B_ 8
#define N_ 4096
#define D_ 1024
#define H_ 8
#define NTOK 4097   // 1 cls + 4096 feat tokens

// ---------------- scratch (static device allocations only) ----------------
__device__ unsigned long long g_best[B_];     // packed (score_key << 32) | ~idx
__device__ float  g_Q[B_*D_];
__device__ float  g_Qp[B_*D_];
__device__ float  g_u[B_*H_*D_];
__device__ __half g_x[(size_t)B_*N_*D_];      // post relu+conv features, fp16 storage
__device__ float  g_logits[B_*H_*NTOK];       // logits -> softmax in place
__device__ float  g_xbar[B_*H_*D_];
__device__ float  g_O[B_*D_];
__device__ float  g_O2[B_*D_];

__device__ __forceinline__ float warp_sum(float v){
    #pragma unroll
    for (int o = 16; o; o >>= 1) v += __shfl_xor_sync(0xffffffffu, v, o);
    return v;
}

__device__ __forceinline__ void h8_to_f(uint4 v, float* f){
    __half2 h0 = *reinterpret_cast<__half2*>(&v.x);
    __half2 h1 = *reinterpret_cast<__half2*>(&v.y);
    __half2 h2 = *reinterpret_cast<__half2*>(&v.z);
    __half2 h3 = *reinterpret_cast<__half2*>(&v.w);
    float2 a = __half22float2(h0); f[0]=a.x; f[1]=a.y;
    float2 b = __half22float2(h1); f[2]=b.x; f[3]=b.y;
    float2 c = __half22float2(h2); f[4]=c.x; f[5]=c.y;
    float2 d = __half22float2(h3); f[6]=d.x; f[7]=d.y;
}

// load float4, relu(v - q) in half2
__device__ __forceinline__ void ld_relu(const float* p, __half2 q0, __half2 q1,
                                        __half2& o0, __half2& o1){
    float4 v = *(const float4*)p;
    __half2 z = __float2half2_rn(0.f);
    o0 = __hmax2(__hsub2(__floats2half2_rn(v.x, v.y), q0), z);
    o1 = __hmax2(__hsub2(__floats2half2_rn(v.z, v.w), q1), z);
}

// ---------------- 0) zero g_u (accumulated atomically each run) ----------------
__global__ void k_init(){
    int id = blockIdx.x*256 + threadIdx.x;
    ((float4*)g_u)[id] = make_float4(0.f,0.f,0.f,0.f);
}

// ---------------- 1) score + fused argmax: per-block packed atomicMax ----------------
__global__ void k_score(const float* __restrict__ inp, const float* __restrict__ wenc){
    int gw   = blockIdx.x*8 + (threadIdx.x >> 5);    // row id (same b within block)
    int lane = threadIdx.x & 31;
    const float4* row = (const float4*)(inp + (size_t)gw * D_);
    const float4* wp  = (const float4*)wenc;
    float acc = 0.f;
    #pragma unroll
    for (int j = 0; j < 8; j++){
        float4 x = row[j*32 + lane];
        float4 w = __ldg(&wp[j*32 + lane]);
        acc += x.x*w.x + x.y*w.y + x.z*w.z + x.w*w.w;
    }
    acc = warp_sum(acc);
    __shared__ unsigned long long sbest[8];
    if (lane == 0){
        unsigned int fb  = __float_as_uint(acc);
        unsigned int key = (fb & 0x80000000u) ? ~fb : (fb | 0x80000000u);
        unsigned int n   = (unsigned int)(gw & (N_-1));
        sbest[threadIdx.x >> 5] = ((unsigned long long)key << 32) | (unsigned long long)(~n);
    }
    __syncthreads();
    if (threadIdx.x == 0){
        unsigned long long m = sbest[0];
        #pragma unroll
        for (int i = 1; i < 8; i++) m = (sbest[i] > m) ? sbest[i] : m;
        atomicMax(&g_best[gw >> 12], m);
    }
}

// ---------------- 2) extract idx, copy Q row ----------------
__global__ void k_prep(const float* __restrict__ inp){
    int b = blockIdx.x;
    unsigned int n = (~(unsigned int)(g_best[b] & 0xffffffffull)) & (N_-1);
    const float* src = inp + ((size_t)b*N_ + n) * D_;
    for (int d = threadIdx.x; d < D_; d += 256) g_Q[b*D_ + d] = src[d];
}

// ---------------- 3) Qp: block per output row j ----------------
__global__ void __launch_bounds__(256) k_qp(const float* __restrict__ Wq, const float* __restrict__ bq){
    int j = blockIdx.x, t = threadIdx.x, lane = t & 31, wp = t >> 5;
    float4 w = __ldg((const float4*)(Wq + (size_t)j * D_) + t);
    float acc[B_];
    #pragma unroll
    for (int b = 0; b < B_; b++){
        float4 q = __ldg((const float4*)(g_Q + b*D_) + t);
        acc[b] = w.x*q.x + w.y*q.y + w.z*q.z + w.w*q.w;
    }
    __shared__ float red[8][B_];
    #pragma unroll
    for (int b = 0; b < B_; b++) acc[b] = warp_sum(acc[b]);
    if (lane == 0){
        #pragma unroll
        for (int b = 0; b < B_; b++) red[wp][b] = acc[b];
    }
    __syncthreads();
    if (t < B_){
        float s = 0.f;
        #pragma unroll
        for (int i = 0; i < 8; i++) s += red[i][t];
        g_Qp[t*D_ + j] = s + bq[j];
    }
}

// ---------------- 4) u[b,h,i] += partial (grid (16,H,4), atomic accumulate) ----------------
__global__ void __launch_bounds__(256) k_u(const float* __restrict__ Wk){
    int h  = blockIdx.y, jc = blockIdx.z;
    int il = threadIdx.x & 63;
    int js = threadIdx.x >> 6;

    __shared__ float qp[B_][32];
    { int t = threadIdx.x;
      qp[t >> 5][t & 31] = g_Qp[(t >> 5)*D_ + h*128 + jc*32 + (t & 31)]; }
    __syncthreads();

    int i = blockIdx.x*64 + il;
    const float* wkp = Wk + (size_t)(h*128 + jc*32 + js*8) * D_ + i;
    float acc[B_];
    #pragma unroll
    for (int b = 0; b < B_; b++) acc[b] = 0.f;
    #pragma unroll
    for (int j = 0; j < 8; j++){
        float w = wkp[(size_t)j * D_];
        #pragma unroll
        for (int b = 0; b < B_; b++) acc[b] += qp[b][js*8 + j] * w;
    }

    __shared__ float part[4][64][B_];
    #pragma unroll
    for (int b = 0; b < B_; b++) part[js][il][b] = acc[b];
    __syncthreads();

    for (int idx = threadIdx.x; idx < 64*B_; idx += 256){
        int ii = idx >> 3, b = idx & 7;
        float s = part[0][ii][b] + part[1][ii][b] + part[2][ii][b] + part[3][ii][b];
        atomicAdd(&g_u[((size_t)(b*H_ + h))*D_ + blockIdx.x*64 + ii], s);
    }
}

// ---------------- 5) relu + depthwise 3x3 conv + residual -> g_x, HALF2 arithmetic ----------------
// 4 channels/thread as 2 half2; residual folded into center tap (+1).
// Block = 16 cg x 16 rows; grid (16, 4 rowblk * 2 wblk, B); 32-w strips.
__global__ void __launch_bounds__(256, 4) k_conv(const float* __restrict__ inp,
                                                 const float* __restrict__ convw,
                                                 const float* __restrict__ convb){
    int b      = blockIdx.z;
    int rowblk = blockIdx.y & 3;
    int wblk   = blockIdx.y >> 2;
    int cg = threadIdx.x & 15;
    int hr = threadIdx.x >> 4;
    int c0 = blockIdx.x*64 + cg*4;
    int h  = rowblk*16 + hr;
    int w0 = wblk*32;

    const float* base = inp + (size_t)b*N_*D_ + c0;
    float4 qf = *(const float4*)(g_Q + b*D_ + c0);
    __half2 q0 = __floats2half2_rn(qf.x, qf.y);
    __half2 q1 = __floats2half2_rn(qf.z, qf.w);
    float4 cf = *(const float4*)(convb + c0);
    __half2 cb0 = __floats2half2_rn(cf.x, cf.y);
    __half2 cb1 = __floats2half2_rn(cf.z, cf.w);

    __half2 wgt[9][2];
    #pragma unroll
    for (int k = 0; k < 9; k++){
        float idk = (k == 4) ? 1.f : 0.f;     // residual folded into center tap
        wgt[k][0] = __floats2half2_rn(convw[(c0+0)*9 + k] + idk, convw[(c0+1)*9 + k] + idk);
        wgt[k][1] = __floats2half2_rn(convw[(c0+2)*9 + k] + idk, convw[(c0+3)*9 + k] + idk);
    }

    bool vld[3];
    const float* rp[3];
    #pragma unroll
    for (int r = 0; r < 3; r++){
        int hh = h - 1 + r;
        vld[r] = (hh >= 0) && (hh < 64);
        int hc = hh < 0 ? 0 : (hh > 63 ? 63 : hh);
        rp[r] = base + (size_t)(hc*64) * D_;
    }

    __half2 Z = __float2half2_rn(0.f);
    __half2 L[3][2], C[3][2], R[3][2];
    #pragma unroll
    for (int r = 0; r < 3; r++){
        if (vld[r]){
            ld_relu(rp[r] + (size_t)w0 * D_, q0, q1, C[r][0], C[r][1]);
            if (w0 > 0) ld_relu(rp[r] + (size_t)(w0-1) * D_, q0, q1, L[r][0], L[r][1]);
            else { L[r][0] = Z; L[r][1] = Z; }
        } else { C[r][0] = Z; C[r][1] = Z; L[r][0] = Z; L[r][1] = Z; }
    }

    __half* outbase = g_x + ((size_t)b*N_ + h*64) * D_ + c0;
    #pragma unroll 8
    for (int w = 0; w < 32; w++){
        int ww = w0 + w;
        #pragma unroll
        for (int r = 0; r < 3; r++){
            if (ww < 63 && vld[r])
                ld_relu(rp[r] + (size_t)(ww + 1) * D_, q0, q1, R[r][0], R[r][1]);
            else { R[r][0] = Z; R[r][1] = Z; }
        }
        __half2 a0 = cb0, a1 = cb1;
        #pragma unroll
        for (int r = 0; r < 3; r++){
            a0 = __hfma2(wgt[r*3+0][0], L[r][0], a0);
            a0 = __hfma2(wgt[r*3+1][0], C[r][0], a0);
            a0 = __hfma2(wgt[r*3+2][0], R[r][0], a0);
            a1 = __hfma2(wgt[r*3+0][1], L[r][1], a1);
            a1 = __hfma2(wgt[r*3+1][1], C[r][1], a1);
            a1 = __hfma2(wgt[r*3+2][1], R[r][1], a1);
        }
        union { uint2 u; __half2 h[2]; } pk;
        pk.h[0] = a0; pk.h[1] = a1;
        *(uint2*)(outbase + (size_t)ww * D_) = pk.u;
        #pragma unroll
        for (int r = 0; r < 3; r++){
            L[r][0] = C[r][0]; L[r][1] = C[r][1];
            C[r][0] = R[r][0]; C[r][1] = R[r][1];
        }
    }
}

// ---------------- 6) logits[b,h,k] = (u[b,h].x_k)/32  (u staged in shared; cb cancels) ----
__global__ void __launch_bounds__(256) k_logits(){
    int b    = blockIdx.y;
    int warp = threadIdx.x >> 5, lane = threadIdx.x & 31;
    int t0   = blockIdx.x*32 + warp*4;

    __shared__ float4 us[2048];           // u[b]: 8 heads x 1024 f32 = 32KB
    {
        const float4* up = (const float4*)(g_u + (size_t)b*H_*D_);
        for (int r = threadIdx.x; r < 2048; r += 256) us[r] = up[r];
    }
    __syncthreads();

    const __half* xbase = g_x + ((size_t)b*N_ + t0) * D_;
    float acc[4][8];
    #pragma unroll
    for (int t = 0; t < 4; t++)
        #pragma unroll
        for (int hh = 0; hh < 8; hh++) acc[t][hh] = 0.f;

    #pragma unroll
    for (int it = 0; it < 4; it++){
        int ck = it*32 + lane;
        float xf[4][8];
        #pragma unroll
        for (int t = 0; t < 4; t++){
            uint4 raw = *(const uint4*)(xbase + (size_t)t*D_ + ck*8);
            h8_to_f(raw, xf[t]);
        }
        #pragma unroll
        for (int hh = 0; hh < 8; hh++){
            float4 u0 = us[hh*256 + ck*2 + 0];
            float4 u1 = us[hh*256 + ck*2 + 1];
            #pragma unroll
            for (int t = 0; t < 4; t++){
                acc[t][hh] += xf[t][0]*u0.x + xf[t][1]*u0.y + xf[t][2]*u0.z + xf[t][3]*u0.w
                            + xf[t][4]*u1.x + xf[t][5]*u1.y + xf[t][6]*u1.z + xf[t][7]*u1.w;
            }
        }
    }
    #pragma unroll
    for (int t = 0; t < 4; t++)
        #pragma unroll
        for (int hh = 0; hh < 8; hh++) acc[t][hh] = warp_sum(acc[t][hh]);

    if (lane < 8){
        #pragma unroll
        for (int t = 0; t < 4; t++)
            g_logits[((size_t)(b*H_ + lane))*NTOK + t0 + t + 1] = acc[t][lane] * 0.03125f;
    }
}

// ---------------- 7) softmax over 4097 (cls logit inline) + init xbar ----------------
__global__ void __launch_bounds__(256) k_softmax(const float* __restrict__ cls){
    int bh = blockIdx.x;
    float* lg = g_logits + (size_t)bh * NTOK;
    __shared__ float sred[8];
    __shared__ float sbc;
    int lane = threadIdx.x & 31, warp = threadIdx.x >> 5;

    // cls logit (k=0): dot(u[bh], cls)/32
    {
        const float* u = g_u + (size_t)bh * D_;
        float a = 0.f;
        for (int d = threadIdx.x; d < D_; d += 256) a += u[d] * cls[d];
        a = warp_sum(a);
        if (lane == 0) sred[warp] = a;
        __syncthreads();
        if (threadIdx.x == 0){
            float s = 0.f;
            #pragma unroll
            for (int i = 0; i < 8; i++) s += sred[i];
            lg[0] = s * 0.03125f;
        }
        __syncthreads();
    }

    float mx = -INFINITY;
    for (int k = threadIdx.x; k < NTOK; k += 256) mx = fmaxf(mx, lg[k]);
    #pragma unroll
    for (int o = 16; o; o >>= 1) mx = fmaxf(mx, __shfl_xor_sync(0xffffffffu, mx, o));
    if (lane == 0) sred[warp] = mx;
    __syncthreads();
    if (threadIdx.x == 0){
        float m = sred[0];
        #pragma unroll
        for (int i = 1; i < 8; i++) m = fmaxf(m, sred[i]);
        sbc = m;
    }
    __syncthreads();
    float m = sbc;

    float sum = 0.f;
    for (int k = threadIdx.x; k < NTOK; k += 256){
        float e = expf(lg[k] - m);
        lg[k] = e;
        sum += e;
    }
    sum = warp_sum(sum);
    if (lane == 0) sred[warp] = sum;
    __syncthreads();
    if (threadIdx.x == 0){
        float s = 0.f;
        #pragma unroll
        for (int i = 0; i < 8; i++) s += sred[i];
        sbc = s;
    }
    __syncthreads();
    float inv = 1.f / sbc;
    for (int k = threadIdx.x; k < NTOK; k += 256) lg[k] *= inv;
    __syncthreads();

    float a0 = lg[0];
    for (int d = threadIdx.x; d < D_; d += 256)
        g_xbar[(size_t)bh * D_ + d] = a0 * cls[d];
}

// ---------------- 8) xbar[b,h,:] += sum_k A[b,h,k] * x_k  (chunk 64, grid 512) ----------------
__global__ void __launch_bounds__(256) k_xbar(){
    int b  = blockIdx.y;
    int k0 = blockIdx.x * 64;
    __shared__ float As[8*64];
    for (int i = threadIdx.x; i < 512; i += 256){
        int hh = i >> 6, kk = i & 63;
        As[i] = g_logits[((size_t)(b*H_ + hh))*NTOK + 1 + k0 + kk];
    }
    __syncthreads();
    const __half* xp = g_x + ((size_t)b*N_ + k0) * D_;
    int d0 = threadIdx.x * 4;
    float4 acc[8];
    #pragma unroll
    for (int hh = 0; hh < 8; hh++) acc[hh] = make_float4(0.f,0.f,0.f,0.f);

    for (int k = 0; k < 64; k++){
        uint2 raw = *(const uint2*)(xp + (size_t)k*D_ + d0);
        __half2 h0 = *reinterpret_cast<__half2*>(&raw.x);
        __half2 h1 = *reinterpret_cast<__half2*>(&raw.y);
        float2 xa = __half22float2(h0);
        float2 xb = __half22float2(h1);
        #pragma unroll
        for (int hh = 0; hh < 8; hh++){
            float a = As[hh*64 + k];
            acc[hh].x += a*xa.x; acc[hh].y += a*xa.y;
            acc[hh].z += a*xb.x; acc[hh].w += a*xb.y;
        }
    }
    #pragma unroll
    for (int hh = 0; hh < 8; hh++){
        float* dst = g_xbar + ((size_t)(b*H_ + hh))*D_ + d0;
        atomicAdd(dst + 0, acc[hh].x);
        atomicAdd(dst + 1, acc[hh].y);
        atomicAdd(dst + 2, acc[hh].z);
        atomicAdd(dst + 3, acc[hh].w);
    }
}

// ---------------- 9) O: block per row j ----------------
__global__ void __launch_bounds__(256) k_O(const float* __restrict__ Wv, const float* __restrict__ bv){
    int j = blockIdx.x, t = threadIdx.x, lane = t & 31, wp = t >> 5;
    int h = j >> 7;
    float4 w = __ldg((const float4*)(Wv + (size_t)j * D_) + t);
    float acc[B_];
    #pragma unroll
    for (int b = 0; b < B_; b++){
        float4 v = __ldg((const float4*)(g_xbar + ((size_t)(b*H_ + h))*D_) + t);
        acc[b] = w.x*v.x + w.y*v.y + w.z*v.z + w.w*v.w;
    }
    __shared__ float red[8][B_];
    #pragma unroll
    for (int b = 0; b < B_; b++) acc[b] = warp_sum(acc[b]);
    if (lane == 0){
        #pragma unroll
        for (int b = 0; b < B_; b++) red[wp][b] = acc[b];
    }
    __syncthreads();
    if (t < B_){
        float s = 0.f;
        #pragma unroll
        for (int i = 0; i < 8; i++) s += red[i][t];
        g_O[t*D_ + j] = g_Qp[t*D_ + j] + bv[j] + s;
    }
}

// ---------------- 10) O2 = O + relu(O @ Wo^T + bo) ----------------
__global__ void __launch_bounds__(256) k_O2(const float* __restrict__ Wo, const float* __restrict__ bo){
    int j = blockIdx.x, t = threadIdx.x, lane = t & 31, wp = t >> 5;
    float4 w = __ldg((const float4*)(Wo + (size_t)j * D_) + t);
    float acc[B_];
    #pragma unroll
    for (int b = 0; b < B_; b++){
        float4 v = __ldg((const float4*)(g_O + (size_t)b*D_) + t);
        acc[b] = w.x*v.x + w.y*v.y + w.z*v.z + w.w*v.w;
    }
    __shared__ float red[8][B_];
    #pragma unroll
    for (int b = 0; b < B_; b++) acc[b] = warp_sum(acc[b]);
    if (lane == 0){
        #pragma unroll
        for (int b = 0; b < B_; b++) red[wp][b] = acc[b];
    }
    __syncthreads();
    if (t < B_){
        float s = 0.f;
        #pragma unroll
        for (int i = 0; i < 8; i++) s += red[i][t];
        g_O2[t*D_ + j] = g_O[t*D_ + j] + fmaxf(s + bo[j], 0.f);
    }
}

// ---------------- 11) out = O2 @ Wfc^T + bfc  -> (8, 2) ----------------
__global__ void k_fc(const float* __restrict__ Wfc, const float* __restrict__ bfc,
                     float* __restrict__ out){
    int b    = blockIdx.x;
    int c    = threadIdx.x >> 5;
    int lane = threadIdx.x & 31;
    const float4* wr = (const float4*)(Wfc + (size_t)c * D_);
    const float4* op = (const float4*)(g_O2 + (size_t)b * D_);
    float acc = 0.f;
    #pragma unroll
    for (int it = 0; it < 8; it++){
        float4 w = wr[it*32 + lane];
        float4 v = op[it*32 + lane];
        acc += w.x*v.x + w.y*v.y + w.z*v.z + w.w*v.w;
    }
    acc = warp_sum(acc);
    if (lane == 0) out[b*2 + c] = acc + bfc[c];
}

// ---------------- stream/event infra (created in global ctor) ----------------
static cudaStream_t s_aux;
static cudaEvent_t  ev_start, ev_q, ev_init, ev_conv;
namespace {
struct _FRMIL_Init {
    _FRMIL_Init(){
        cudaStreamCreateWithFlags(&s_aux, cudaStreamNonBlocking);
        cudaEventCreateWithFlags(&ev_start, cudaEventDisableTiming);
        cudaEventCreateWithFlags(&ev_q,     cudaEventDisableTiming);
        cudaEventCreateWithFlags(&ev_init,  cudaEventDisableTiming);
        cudaEventCreateWithFlags(&ev_conv,  cudaEventDisableTiming);
    }
} _frmil_init_;
}

// ---------------- launcher ----------------
extern "C" void kernel_launch(void* const* d_in, const int* in_sizes, int n_in,
                              void* d_out, int out_size){
    const float* inputs = (const float*)d_in[0];
    const float* Wenc   = (const float*)d_in[1];
    // d_in[2] = b_enc : constant shift through sigmoid, irrelevant for argmax
    const float* cls    = (const float*)d_in[3];
    const float* convw  = (const float*)d_in[4];
    const float* convb  = (const float*)d_in[5];
    const float* Wq     = (const float*)d_in[6];
    const float* bq     = (const float*)d_in[7];
    const float* Wk     = (const float*)d_in[8];
    // d_in[9] = bk : constant per (b,h) logit offset -> cancels in softmax
    const float* Wv     = (const float*)d_in[10];
    const float* bv     = (const float*)d_in[11];
    const float* Wo     = (const float*)d_in[12];
    const float* bo     = (const float*)d_in[13];
    const float* Wfc    = (const float*)d_in[14];
    const float* bfc    = (const float*)d_in[15];
    float* out = (float*)d_out;

    // fork: aux stream zeroes g_u while main streams scores
    cudaEventRecord(ev_start, 0);
    cudaStreamWaitEvent(s_aux, ev_start, 0);
    k_init <<<64, 256, 0, s_aux>>>();
    cudaEventRecord(ev_init, s_aux);

    k_score<<<B_*N_/8, 256>>>(inputs, Wenc);
    k_prep <<<B_, 256>>>(inputs);
    cudaEventRecord(ev_q, 0);

    // aux: conv (the long pole) overlaps qp+u on main
    cudaStreamWaitEvent(s_aux, ev_q, 0);
    k_conv <<<dim3(16, 8, B_), 256, 0, s_aux>>>(inputs, convw, convb);
    cudaEventRecord(ev_conv, s_aux);

    k_qp   <<<D_, 256>>>(Wq, bq);
    cudaStreamWaitEvent(0, ev_init, 0);
    k_u    <<<dim3(16, H_, 4), 256>>>(Wk);

    // join: logits needs conv output + u
    cudaStreamWaitEvent(0, ev_conv, 0);
    k_logits <<<dim3(N_/32, B_), 256>>>();
    k_softmax<<<B_*H_, 256>>>(cls);
    k_xbar   <<<dim3(N_/64, B_), 256>>>();
    k_O      <<<D_, 256>>>(Wv, bv);
    k_O2     <<<D_, 256>>>(Wo, bo);
    k_fc     <<<B_, 64>>>(Wfc, bfc, out);
}

// round 7
// speedup vs baseline: 1.2344x; 1.0640x over previous
#include <cuda_runtime.h>
#include <cuda_fp16.h>
#include <math.h>

#define B_ 8
#define N_ 4096
#define D_ 1024
#define H_ 8
#define NTOK 4097   // 1 cls + 4096 feat tokens

// ---------------- scratch (static device allocations only) ----------------
__device__ unsigned long long g_best[B_];     // packed (score_key << 32) | ~idx
__device__ float  g_Q[B_*D_];
__device__ float  g_Qp[B_*D_];
__device__ float  g_u[B_*H_*D_];
__device__ __half g_x[(size_t)B_*N_*D_];      // post relu+conv features, fp16 storage
__device__ float  g_logits[B_*H_*NTOK];       // logits -> softmax in place
__device__ float  g_xbar[B_*H_*D_];
__device__ float  g_O[B_*D_];
__device__ float  g_O2[B_*D_];

__device__ __forceinline__ float warp_sum(float v){
    #pragma unroll
    for (int o = 16; o; o >>= 1) v += __shfl_xor_sync(0xffffffffu, v, o);
    return v;
}

__device__ __forceinline__ void h8_to_f(uint4 v, float* f){
    __half2 h0 = *reinterpret_cast<__half2*>(&v.x);
    __half2 h1 = *reinterpret_cast<__half2*>(&v.y);
    __half2 h2 = *reinterpret_cast<__half2*>(&v.z);
    __half2 h3 = *reinterpret_cast<__half2*>(&v.w);
    float2 a = __half22float2(h0); f[0]=a.x; f[1]=a.y;
    float2 b = __half22float2(h1); f[2]=b.x; f[3]=b.y;
    float2 c = __half22float2(h2); f[4]=c.x; f[5]=c.y;
    float2 d = __half22float2(h3); f[6]=d.x; f[7]=d.y;
}

// load float2 (2 channels), relu(v - q) in half2
__device__ __forceinline__ __half2 ld_relu2(const float* p, __half2 q){
    float2 v = *(const float2*)p;
    return __hmax2(__hsub2(__floats2half2_rn(v.x, v.y), q), __float2half2_rn(0.f));
}

// ---------------- 0) zero g_u (accumulated atomically each run) ----------------
__global__ void k_init(){
    int id = blockIdx.x*256 + threadIdx.x;
    ((float4*)g_u)[id] = make_float4(0.f,0.f,0.f,0.f);
}

// ---------------- 1) score + fused argmax: per-block packed atomicMax ----------------
__global__ void k_score(const float* __restrict__ inp, const float* __restrict__ wenc){
    int gw   = blockIdx.x*8 + (threadIdx.x >> 5);    // row id (same b within block)
    int lane = threadIdx.x & 31;
    const float4* row = (const float4*)(inp + (size_t)gw * D_);
    const float4* wp  = (const float4*)wenc;
    float acc = 0.f;
    #pragma unroll
    for (int j = 0; j < 8; j++){
        float4 x = row[j*32 + lane];
        float4 w = __ldg(&wp[j*32 + lane]);
        acc += x.x*w.x + x.y*w.y + x.z*w.z + x.w*w.w;
    }
    acc = warp_sum(acc);
    __shared__ unsigned long long sbest[8];
    if (lane == 0){
        unsigned int fb  = __float_as_uint(acc);
        unsigned int key = (fb & 0x80000000u) ? ~fb : (fb | 0x80000000u);
        unsigned int n   = (unsigned int)(gw & (N_-1));
        sbest[threadIdx.x >> 5] = ((unsigned long long)key << 32) | (unsigned long long)(~n);
    }
    __syncthreads();
    if (threadIdx.x == 0){
        unsigned long long m = sbest[0];
        #pragma unroll
        for (int i = 1; i < 8; i++) m = (sbest[i] > m) ? sbest[i] : m;
        atomicMax(&g_best[gw >> 12], m);
    }
}

// ---------------- 2) extract idx, copy Q row ----------------
__global__ void k_prep(const float* __restrict__ inp){
    int b = blockIdx.x;
    unsigned int n = (~(unsigned int)(g_best[b] & 0xffffffffull)) & (N_-1);
    const float* src = inp + ((size_t)b*N_ + n) * D_;
    for (int d = threadIdx.x; d < D_; d += 256) g_Q[b*D_ + d] = src[d];
}

// ---------------- 3) Qp: block per output row j ----------------
__global__ void __launch_bounds__(256) k_qp(const float* __restrict__ Wq, const float* __restrict__ bq){
    int j = blockIdx.x, t = threadIdx.x, lane = t & 31, wp = t >> 5;
    float4 w = __ldg((const float4*)(Wq + (size_t)j * D_) + t);
    float acc[B_];
    #pragma unroll
    for (int b = 0; b < B_; b++){
        float4 q = __ldg((const float4*)(g_Q + b*D_) + t);
        acc[b] = w.x*q.x + w.y*q.y + w.z*q.z + w.w*q.w;
    }
    __shared__ float red[8][B_];
    #pragma unroll
    for (int b = 0; b < B_; b++) acc[b] = warp_sum(acc[b]);
    if (lane == 0){
        #pragma unroll
        for (int b = 0; b < B_; b++) red[wp][b] = acc[b];
    }
    __syncthreads();
    if (t < B_){
        float s = 0.f;
        #pragma unroll
        for (int i = 0; i < 8; i++) s += red[i][t];
        g_Qp[t*D_ + j] = s + bq[j];
    }
}

// ---------------- 4) u[b,h,i] += partial (grid (16,H,4), atomic accumulate) ----------------
__global__ void __launch_bounds__(256) k_u(const float* __restrict__ Wk){
    int h  = blockIdx.y, jc = blockIdx.z;
    int il = threadIdx.x & 63;
    int js = threadIdx.x >> 6;

    __shared__ float qp[B_][32];
    { int t = threadIdx.x;
      qp[t >> 5][t & 31] = g_Qp[(t >> 5)*D_ + h*128 + jc*32 + (t & 31)]; }
    __syncthreads();

    int i = blockIdx.x*64 + il;
    const float* wkp = Wk + (size_t)(h*128 + jc*32 + js*8) * D_ + i;
    float acc[B_];
    #pragma unroll
    for (int b = 0; b < B_; b++) acc[b] = 0.f;
    #pragma unroll
    for (int j = 0; j < 8; j++){
        float w = wkp[(size_t)j * D_];
        #pragma unroll
        for (int b = 0; b < B_; b++) acc[b] += qp[b][js*8 + j] * w;
    }

    __shared__ float part[4][64][B_];
    #pragma unroll
    for (int b = 0; b < B_; b++) part[js][il][b] = acc[b];
    __syncthreads();

    for (int idx = threadIdx.x; idx < 64*B_; idx += 256){
        int ii = idx >> 3, b = idx & 7;
        float s = part[0][ii][b] + part[1][ii][b] + part[2][ii][b] + part[3][ii][b];
        atomicAdd(&g_u[((size_t)(b*H_ + h))*D_ + blockIdx.x*64 + ii], s);
    }
}

// ---------------- 5) relu + depthwise 3x3 conv + residual -> g_x, HALF2 arithmetic v3 ----------------
// 2 output rows x 2 channels per thread; 4 input rows shared across the 2 outputs.
// Residual UNFOLDED (pure taps, += C at end) for precision.
// Block = 32 cg (64 ch) x 8 row-pairs (16 rows); full 64-w register slide. Grid (16, 4, B).
__global__ void __launch_bounds__(256, 4) k_conv(const float* __restrict__ inp,
                                                 const float* __restrict__ convw,
                                                 const float* __restrict__ convb){
    int b  = blockIdx.z;
    int cg = threadIdx.x & 31;
    int tr = threadIdx.x >> 5;
    int c0 = blockIdx.x*64 + cg*2;
    int h0 = blockIdx.y*16 + tr*2;          // output rows h0, h0+1

    const float* base = inp + (size_t)b*N_*D_ + c0;
    float2 qf = *(const float2*)(g_Q + b*D_ + c0);
    __half2 q  = __floats2half2_rn(qf.x, qf.y);
    float2 cf = *(const float2*)(convb + c0);
    __half2 cb = __floats2half2_rn(cf.x, cf.y);

    __half2 wgt[9];
    #pragma unroll
    for (int k = 0; k < 9; k++)
        wgt[k] = __floats2half2_rn(convw[(c0+0)*9 + k], convw[(c0+1)*9 + k]);

    // 4 input rows: h0-1, h0, h0+1, h0+2
    bool vld[4];
    const float* rp[4];
    #pragma unroll
    for (int r = 0; r < 4; r++){
        int hh = h0 - 1 + r;
        vld[r] = (hh >= 0) && (hh < 64);
        int hc = hh < 0 ? 0 : (hh > 63 ? 63 : hh);
        rp[r] = base + (size_t)(hc*64) * D_;
    }

    __half2 Z = __float2half2_rn(0.f);
    __half2 L[4], C[4], R[4];
    #pragma unroll
    for (int r = 0; r < 4; r++){
        L[r] = Z;
        C[r] = vld[r] ? ld_relu2(rp[r], q) : Z;
    }

    __half* out0 = g_x + ((size_t)b*N_ + h0*64) * D_ + c0;
    __half* out1 = out0 + (size_t)64 * D_;
    #pragma unroll 4
    for (int w = 0; w < 64; w++){
        #pragma unroll
        for (int r = 0; r < 4; r++)
            R[r] = (w < 63 && vld[r]) ? ld_relu2(rp[r] + (size_t)(w+1) * D_, q) : Z;

        __half2 a0 = cb, a1 = cb;
        #pragma unroll
        for (int r = 0; r < 3; r++){
            a0 = __hfma2(wgt[r*3+0], L[r],   a0);
            a0 = __hfma2(wgt[r*3+1], C[r],   a0);
            a0 = __hfma2(wgt[r*3+2], R[r],   a0);
            a1 = __hfma2(wgt[r*3+0], L[r+1], a1);
            a1 = __hfma2(wgt[r*3+1], C[r+1], a1);
            a1 = __hfma2(wgt[r*3+2], R[r+1], a1);
        }
        *(__half2*)(out0 + (size_t)w * D_) = __hadd2(a0, C[1]);   // residual: + relu row h0
        *(__half2*)(out1 + (size_t)w * D_) = __hadd2(a1, C[2]);   // residual: + relu row h0+1
        #pragma unroll
        for (int r = 0; r < 4; r++){ L[r] = C[r]; C[r] = R[r]; }
    }
}

// ---------------- 6) logits[b,h,k] = (u[b,h].x_k)/32  (u staged in shared; cb cancels) ----
__global__ void __launch_bounds__(256) k_logits(){
    int b    = blockIdx.y;
    int warp = threadIdx.x >> 5, lane = threadIdx.x & 31;
    int t0   = blockIdx.x*32 + warp*4;

    __shared__ float4 us[2048];           // u[b]: 8 heads x 1024 f32 = 32KB
    {
        const float4* up = (const float4*)(g_u + (size_t)b*H_*D_);
        for (int r = threadIdx.x; r < 2048; r += 256) us[r] = up[r];
    }
    __syncthreads();

    const __half* xbase = g_x + ((size_t)b*N_ + t0) * D_;
    float acc[4][8];
    #pragma unroll
    for (int t = 0; t < 4; t++)
        #pragma unroll
        for (int hh = 0; hh < 8; hh++) acc[t][hh] = 0.f;

    #pragma unroll
    for (int it = 0; it < 4; it++){
        int ck = it*32 + lane;
        float xf[4][8];
        #pragma unroll
        for (int t = 0; t < 4; t++){
            uint4 raw = *(const uint4*)(xbase + (size_t)t*D_ + ck*8);
            h8_to_f(raw, xf[t]);
        }
        #pragma unroll
        for (int hh = 0; hh < 8; hh++){
            float4 u0 = us[hh*256 + ck*2 + 0];
            float4 u1 = us[hh*256 + ck*2 + 1];
            #pragma unroll
            for (int t = 0; t < 4; t++){
                acc[t][hh] += xf[t][0]*u0.x + xf[t][1]*u0.y + xf[t][2]*u0.z + xf[t][3]*u0.w
                            + xf[t][4]*u1.x + xf[t][5]*u1.y + xf[t][6]*u1.z + xf[t][7]*u1.w;
            }
        }
    }
    #pragma unroll
    for (int t = 0; t < 4; t++)
        #pragma unroll
        for (int hh = 0; hh < 8; hh++) acc[t][hh] = warp_sum(acc[t][hh]);

    if (lane < 8){
        #pragma unroll
        for (int t = 0; t < 4; t++)
            g_logits[((size_t)(b*H_ + lane))*NTOK + t0 + t + 1] = acc[t][lane] * 0.03125f;
    }
}

// ---------------- 7) softmax over 4097 (cls logit inline) + init xbar ----------------
__global__ void __launch_bounds__(256) k_softmax(const float* __restrict__ cls){
    int bh = blockIdx.x;
    float* lg = g_logits + (size_t)bh * NTOK;
    __shared__ float sred[8];
    __shared__ float sbc;
    int lane = threadIdx.x & 31, warp = threadIdx.x >> 5;

    // cls logit (k=0): dot(u[bh], cls)/32
    {
        const float* u = g_u + (size_t)bh * D_;
        float a = 0.f;
        for (int d = threadIdx.x; d < D_; d += 256) a += u[d] * cls[d];
        a = warp_sum(a);
        if (lane == 0) sred[warp] = a;
        __syncthreads();
        if (threadIdx.x == 0){
            float s = 0.f;
            #pragma unroll
            for (int i = 0; i < 8; i++) s += sred[i];
            lg[0] = s * 0.03125f;
        }
        __syncthreads();
    }

    float mx = -INFINITY;
    for (int k = threadIdx.x; k < NTOK; k += 256) mx = fmaxf(mx, lg[k]);
    #pragma unroll
    for (int o = 16; o; o >>= 1) mx = fmaxf(mx, __shfl_xor_sync(0xffffffffu, mx, o));
    if (lane == 0) sred[warp] = mx;
    __syncthreads();
    if (threadIdx.x == 0){
        float m = sred[0];
        #pragma unroll
        for (int i = 1; i < 8; i++) m = fmaxf(m, sred[i]);
        sbc = m;
    }
    __syncthreads();
    float m = sbc;

    float sum = 0.f;
    for (int k = threadIdx.x; k < NTOK; k += 256){
        float e = expf(lg[k] - m);
        lg[k] = e;
        sum += e;
    }
    sum = warp_sum(sum);
    if (lane == 0) sred[warp] = sum;
    __syncthreads();
    if (threadIdx.x == 0){
        float s = 0.f;
        #pragma unroll
        for (int i = 0; i < 8; i++) s += sred[i];
        sbc = s;
    }
    __syncthreads();
    float inv = 1.f / sbc;
    for (int k = threadIdx.x; k < NTOK; k += 256) lg[k] *= inv;
    __syncthreads();

    float a0 = lg[0];
    for (int d = threadIdx.x; d < D_; d += 256)
        g_xbar[(size_t)bh * D_ + d] = a0 * cls[d];
}

// ---------------- 8) xbar[b,h,:] += sum_k A[b,h,k] * x_k  (chunk 64, grid 512) ----------------
__global__ void __launch_bounds__(256) k_xbar(){
    int b  = blockIdx.y;
    int k0 = blockIdx.x * 64;
    __shared__ float As[8*64];
    for (int i = threadIdx.x; i < 512; i += 256){
        int hh = i >> 6, kk = i & 63;
        As[i] = g_logits[((size_t)(b*H_ + hh))*NTOK + 1 + k0 + kk];
    }
    __syncthreads();
    const __half* xp = g_x + ((size_t)b*N_ + k0) * D_;
    int d0 = threadIdx.x * 4;
    float4 acc[8];
    #pragma unroll
    for (int hh = 0; hh < 8; hh++) acc[hh] = make_float4(0.f,0.f,0.f,0.f);

    for (int k = 0; k < 64; k++){
        uint2 raw = *(const uint2*)(xp + (size_t)k*D_ + d0);
        __half2 h0 = *reinterpret_cast<__half2*>(&raw.x);
        __half2 h1 = *reinterpret_cast<__half2*>(&raw.y);
        float2 xa = __half22float2(h0);
        float2 xb = __half22float2(h1);
        #pragma unroll
        for (int hh = 0; hh < 8; hh++){
            float a = As[hh*64 + k];
            acc[hh].x += a*xa.x; acc[hh].y += a*xa.y;
            acc[hh].z += a*xb.x; acc[hh].w += a*xb.y;
        }
    }
    #pragma unroll
    for (int hh = 0; hh < 8; hh++){
        float* dst = g_xbar + ((size_t)(b*H_ + hh))*D_ + d0;
        atomicAdd(dst + 0, acc[hh].x);
        atomicAdd(dst + 1, acc[hh].y);
        atomicAdd(dst + 2, acc[hh].z);
        atomicAdd(dst + 3, acc[hh].w);
    }
}

// ---------------- 9) O: block per row j ----------------
__global__ void __launch_bounds__(256) k_O(const float* __restrict__ Wv, const float* __restrict__ bv){
    int j = blockIdx.x, t = threadIdx.x, lane = t & 31, wp = t >> 5;
    int h = j >> 7;
    float4 w = __ldg((const float4*)(Wv + (size_t)j * D_) + t);
    float acc[B_];
    #pragma unroll
    for (int b = 0; b < B_; b++){
        float4 v = __ldg((const float4*)(g_xbar + ((size_t)(b*H_ + h))*D_) + t);
        acc[b] = w.x*v.x + w.y*v.y + w.z*v.z + w.w*v.w;
    }
    __shared__ float red[8][B_];
    #pragma unroll
    for (int b = 0; b < B_; b++) acc[b] = warp_sum(acc[b]);
    if (lane == 0){
        #pragma unroll
        for (int b = 0; b < B_; b++) red[wp][b] = acc[b];
    }
    __syncthreads();
    if (t < B_){
        float s = 0.f;
        #pragma unroll
        for (int i = 0; i < 8; i++) s += red[i][t];
        g_O[t*D_ + j] = g_Qp[t*D_ + j] + bv[j] + s;
    }
}

// ---------------- 10) O2 = O + relu(O @ Wo^T + bo) ----------------
__global__ void __launch_bounds__(256) k_O2(const float* __restrict__ Wo, const float* __restrict__ bo){
    int j = blockIdx.x, t = threadIdx.x, lane = t & 31, wp = t >> 5;
    float4 w = __ldg((const float4*)(Wo + (size_t)j * D_) + t);
    float acc[B_];
    #pragma unroll
    for (int b = 0; b < B_; b++){
        float4 v = __ldg((const float4*)(g_O + (size_t)b*D_) + t);
        acc[b] = w.x*v.x + w.y*v.y + w.z*v.z + w.w*v.w;
    }
    __shared__ float red[8][B_];
    #pragma unroll
    for (int b = 0; b < B_; b++) acc[b] = warp_sum(acc[b]);
    if (lane == 0){
        #pragma unroll
        for (int b = 0; b < B_; b++) red[wp][b] = acc[b];
    }
    __syncthreads();
    if (t < B_){
        float s = 0.f;
        #pragma unroll
        for (int i = 0; i < 8; i++) s += red[i][t];
        g_O2[t*D_ + j] = g_O[t*D_ + j] + fmaxf(s + bo[j], 0.f);
    }
}

// ---------------- 11) out = O2 @ Wfc^T + bfc  -> (8, 2) ----------------
__global__ void k_fc(const float* __restrict__ Wfc, const float* __restrict__ bfc,
                     float* __restrict__ out){
    int b    = blockIdx.x;
    int c    = threadIdx.x >> 5;
    int lane = threadIdx.x & 31;
    const float4* wr = (const float4*)(Wfc + (size_t)c * D_);
    const float4* op = (const float4*)(g_O2 + (size_t)b * D_);
    float acc = 0.f;
    #pragma unroll
    for (int it = 0; it < 8; it++){
        float4 w = wr[it*32 + lane];
        float4 v = op[it*32 + lane];
        acc += w.x*v.x + w.y*v.y + w.z*v.z + w.w*v.w;
    }
    acc = warp_sum(acc);
    if (lane == 0) out[b*2 + c] = acc + bfc[c];
}

// ---------------- stream/event infra (created in global ctor) ----------------
static cudaStream_t s_aux;
static cudaEvent_t  ev_start, ev_q, ev_init, ev_conv;
namespace {
struct _FRMIL_Init {
    _FRMIL_Init(){
        cudaStreamCreateWithFlags(&s_aux, cudaStreamNonBlocking);
        cudaEventCreateWithFlags(&ev_start, cudaEventDisableTiming);
        cudaEventCreateWithFlags(&ev_q,     cudaEventDisableTiming);
        cudaEventCreateWithFlags(&ev_init,  cudaEventDisableTiming);
        cudaEventCreateWithFlags(&ev_conv,  cudaEventDisableTiming);
    }
} _frmil_init_;
}

// ---------------- launcher ----------------
extern "C" void kernel_launch(void* const* d_in, const int* in_sizes, int n_in,
                              void* d_out, int out_size){
    const float* inputs = (const float*)d_in[0];
    const float* Wenc   = (const float*)d_in[1];
    // d_in[2] = b_enc : constant shift through sigmoid, irrelevant for argmax
    const float* cls    = (const float*)d_in[3];
    const float* convw  = (const float*)d_in[4];
    const float* convb  = (const float*)d_in[5];
    const float* Wq     = (const float*)d_in[6];
    const float* bq     = (const float*)d_in[7];
    const float* Wk     = (const float*)d_in[8];
    // d_in[9] = bk : constant per (b,h) logit offset -> cancels in softmax
    const float* Wv     = (const float*)d_in[10];
    const float* bv     = (const float*)d_in[11];
    const float* Wo     = (const float*)d_in[12];
    const float* bo     = (const float*)d_in[13];
    const float* Wfc    = (const float*)d_in[14];
    const float* bfc    = (const float*)d_in[15];
    float* out = (float*)d_out;

    // fork: aux stream zeroes g_u while main streams scores
    cudaEventRecord(ev_start, 0);
    cudaStreamWaitEvent(s_aux, ev_start, 0);
    k_init <<<64, 256, 0, s_aux>>>();
    cudaEventRecord(ev_init, s_aux);

    k_score<<<B_*N_/8, 256>>>(inputs, Wenc);
    k_prep <<<B_, 256>>>(inputs);
    cudaEventRecord(ev_q, 0);

    // aux: conv (the long pole) overlaps qp+u on main
    cudaStreamWaitEvent(s_aux, ev_q, 0);
    k_conv <<<dim3(16, 4, B_), 256, 0, s_aux>>>(inputs, convw, convb);
    cudaEventRecord(ev_conv, s_aux);

    k_qp   <<<D_, 256>>>(Wq, bq);
    cudaStreamWaitEvent(0, ev_init, 0);
    k_u    <<<dim3(16, H_, 4), 256>>>(Wk);

    // join: logits needs conv output + u
    cudaStreamWaitEvent(0, ev_conv, 0);
    k_logits <<<dim3(N_/32, B_), 256>>>();
    k_softmax<<<B_*H_, 256>>>(cls);
    k_xbar   <<<dim3(N_/64, B_), 256>>>();
    k_O      <<<D_, 256>>>(Wv, bv);
    k_O2     <<<D_, 256>>>(Wo, bo);
    k_fc     <<<B_, 64>>>(Wfc, bfc, out);
}

// round 8
// speedup vs baseline: 1.3201x; 1.0694x over previous
#include <cuda_runtime.h>
#include <cuda_fp16.h>
#include <mma.h>
#include <math.h>

using namespace nvcuda;

#define B_ 8
#define N_ 4096
#define D_ 1024
#define H_ 8
#define NTOK 4097   // 1 cls + 4096 feat tokens

// ---------------- scratch (static device allocations only) ----------------
__device__ unsigned long long g_best[B_];     // packed (score_key << 32) | ~idx
__device__ int    g_tick[B_];                 // score completion tickets (self-resetting)
__device__ float  g_Q[B_*D_];
__device__ float  g_Qp[B_*D_];
__device__ float  g_u[B_*H_*D_];
__device__ __half g_u16[B_*D_*16];            // u fp16, [b][d][16 head-pad]; heads 8-15 stay 0
__device__ __half g_x[(size_t)B_*N_*D_];      // post relu+conv features, fp16
__device__ float  g_logits[B_*H_*NTOK];
__device__ __half g_A16[(size_t)B_*16*4096];  // softmax weights fp16 [b][16 head-pad][token]; rows 8-15 stay 0
__device__ float  g_xbar[B_*16*D_];           // [b][16 head-pad][d]
__device__ float  g_O[B_*D_];
__device__ float  g_O2[B_*D_];

__device__ __forceinline__ float warp_sum(float v){
    #pragma unroll
    for (int o = 16; o; o >>= 1) v += __shfl_xor_sync(0xffffffffu, v, o);
    return v;
}

// load float2 (2 channels), relu(v - q) in half2
__device__ __forceinline__ __half2 ld_relu2(const float* p, __half2 q){
    float2 v = *(const float2*)p;
    return __hmax2(__hsub2(__floats2half2_rn(v.x, v.y), q), __float2half2_rn(0.f));
}

// ---------------- 1) score + fused argmax + fused g_u zero + fused Q copy ----------------
__global__ void k_score(const float* __restrict__ inp, const float* __restrict__ wenc){
    int gw   = blockIdx.x*8 + (threadIdx.x >> 5);    // row id (same batch within block)
    int lane = threadIdx.x & 31;
    int b    = blockIdx.x >> 9;                      // 512 blocks per batch

    // zero g_u slice: 16384 float4 total / 4096 blocks = 4 each
    if (threadIdx.x < 4)
        ((float4*)g_u)[blockIdx.x*4 + threadIdx.x] = make_float4(0.f,0.f,0.f,0.f);

    const float4* row = (const float4*)(inp + (size_t)gw * D_);
    const float4* wp  = (const float4*)wenc;
    float acc = 0.f;
    #pragma unroll
    for (int j = 0; j < 8; j++){
        float4 x = row[j*32 + lane];
        float4 w = __ldg(&wp[j*32 + lane]);
        acc += x.x*w.x + x.y*w.y + x.z*w.z + x.w*w.w;
    }
    acc = warp_sum(acc);
    __shared__ unsigned long long sbest[8];
    if (lane == 0){
        unsigned int fb  = __float_as_uint(acc);
        unsigned int key = (fb & 0x80000000u) ? ~fb : (fb | 0x80000000u);
        unsigned int n   = (unsigned int)(gw & (N_-1));
        sbest[threadIdx.x >> 5] = ((unsigned long long)key << 32) | (unsigned long long)(~n);
    }
    __syncthreads();
    __shared__ int slast;
    if (threadIdx.x == 0){
        unsigned long long m = sbest[0];
        #pragma unroll
        for (int i = 1; i < 8; i++) m = (sbest[i] > m) ? sbest[i] : m;
        atomicMax(&g_best[b], m);
        __threadfence();
        slast = (atomicAdd(&g_tick[b], 1) == 511);
    }
    __syncthreads();
    if (slast){
        __threadfence();
        unsigned int n = (~(unsigned int)(g_best[b] & 0xffffffffull)) & (N_-1);
        const float4* src = (const float4*)(inp + ((size_t)b*N_ + n) * D_);
        float4* dq = (float4*)(g_Q + b*D_);
        dq[threadIdx.x] = src[threadIdx.x];
        if (threadIdx.x == 0) g_tick[b] = 0;     // reset for next replay
    }
}

// ---------------- 2) Qp: block per output row j ----------------
__global__ void __launch_bounds__(256) k_qp(const float* __restrict__ Wq, const float* __restrict__ bq){
    int j = blockIdx.x, t = threadIdx.x, lane = t & 31, wp = t >> 5;
    float4 w = __ldg((const float4*)(Wq + (size_t)j * D_) + t);
    float acc[B_];
    #pragma unroll
    for (int b = 0; b < B_; b++){
        float4 q = __ldg((const float4*)(g_Q + b*D_) + t);
        acc[b] = w.x*q.x + w.y*q.y + w.z*q.z + w.w*q.w;
    }
    __shared__ float red[8][B_];
    #pragma unroll
    for (int b = 0; b < B_; b++) acc[b] = warp_sum(acc[b]);
    if (lane == 0){
        #pragma unroll
        for (int b = 0; b < B_; b++) red[wp][b] = acc[b];
    }
    __syncthreads();
    if (t < B_){
        float s = 0.f;
        #pragma unroll
        for (int i = 0; i < 8; i++) s += red[i][t];
        g_Qp[t*D_ + j] = s + bq[j];
    }
}

// ---------------- 3) u[b,h,i] += partial (grid (16,H,4), atomic accumulate) ----------------
__global__ void __launch_bounds__(256) k_u(const float* __restrict__ Wk){
    int h  = blockIdx.y, jc = blockIdx.z;
    int il = threadIdx.x & 63;
    int js = threadIdx.x >> 6;

    __shared__ float qp[B_][32];
    { int t = threadIdx.x;
      qp[t >> 5][t & 31] = g_Qp[(t >> 5)*D_ + h*128 + jc*32 + (t & 31)]; }
    __syncthreads();

    int i = blockIdx.x*64 + il;
    const float* wkp = Wk + (size_t)(h*128 + jc*32 + js*8) * D_ + i;
    float acc[B_];
    #pragma unroll
    for (int b = 0; b < B_; b++) acc[b] = 0.f;
    #pragma unroll
    for (int j = 0; j < 8; j++){
        float w = wkp[(size_t)j * D_];
        #pragma unroll
        for (int b = 0; b < B_; b++) acc[b] += qp[b][js*8 + j] * w;
    }

    __shared__ float part[4][64][B_];
    #pragma unroll
    for (int b = 0; b < B_; b++) part[js][il][b] = acc[b];
    __syncthreads();

    for (int idx = threadIdx.x; idx < 64*B_; idx += 256){
        int ii = idx >> 3, b = idx & 7;
        float s = part[0][ii][b] + part[1][ii][b] + part[2][ii][b] + part[3][ii][b];
        atomicAdd(&g_u[((size_t)(b*H_ + h))*D_ + blockIdx.x*64 + ii], s);
    }
}

// ---------------- 4) u -> fp16 transpose [b][d][16]; heads 8..15 remain 0 ----------------
__global__ void k_u16(){
    int idx = blockIdx.x*256 + threadIdx.x;   // 8192 (b,d) pairs
    int b = idx >> 10, d = idx & 1023;
    __half h8[8];
    #pragma unroll
    for (int h = 0; h < 8; h++)
        h8[h] = __float2half(g_u[(((size_t)(b*H_ + h)) << 10) | d]);
    __half* dst = g_u16 + (size_t)idx * 16;
    *(uint4*)dst = *(uint4*)h8;               // heads 0-7
    *(uint4*)(dst + 8) = make_uint4(0,0,0,0); // heads 8-15 = 0
}

// ---------------- 5) relu + depthwise 3x3 conv + residual -> g_x (HFMA2, 2 rows x 2 ch) ----------------
__global__ void __launch_bounds__(256, 4) k_conv(const float* __restrict__ inp,
                                                 const float* __restrict__ convw,
                                                 const float* __restrict__ convb){
    int b  = blockIdx.z;
    int cg = threadIdx.x & 31;
    int tr = threadIdx.x >> 5;
    int c0 = blockIdx.x*64 + cg*2;
    int h0 = blockIdx.y*16 + tr*2;

    const float* base = inp + (size_t)b*N_*D_ + c0;
    float2 qf = *(const float2*)(g_Q + b*D_ + c0);
    __half2 q  = __floats2half2_rn(qf.x, qf.y);
    float2 cf = *(const float2*)(convb + c0);
    __half2 cb = __floats2half2_rn(cf.x, cf.y);

    __half2 wgt[9];
    #pragma unroll
    for (int k = 0; k < 9; k++)
        wgt[k] = __floats2half2_rn(convw[(c0+0)*9 + k], convw[(c0+1)*9 + k]);

    bool vld[4];
    const float* rp[4];
    #pragma unroll
    for (int r = 0; r < 4; r++){
        int hh = h0 - 1 + r;
        vld[r] = (hh >= 0) && (hh < 64);
        int hc = hh < 0 ? 0 : (hh > 63 ? 63 : hh);
        rp[r] = base + (size_t)(hc*64) * D_;
    }

    __half2 Z = __float2half2_rn(0.f);
    __half2 L[4], C[4], R[4];
    #pragma unroll
    for (int r = 0; r < 4; r++){
        L[r] = Z;
        C[r] = vld[r] ? ld_relu2(rp[r], q) : Z;
    }

    __half* out0 = g_x + ((size_t)b*N_ + h0*64) * D_ + c0;
    __half* out1 = out0 + (size_t)64 * D_;
    #pragma unroll 4
    for (int w = 0; w < 64; w++){
        #pragma unroll
        for (int r = 0; r < 4; r++)
            R[r] = (w < 63 && vld[r]) ? ld_relu2(rp[r] + (size_t)(w+1) * D_, q) : Z;

        __half2 a0 = cb, a1 = cb;
        #pragma unroll
        for (int r = 0; r < 3; r++){
            a0 = __hfma2(wgt[r*3+0], L[r],   a0);
            a0 = __hfma2(wgt[r*3+1], C[r],   a0);
            a0 = __hfma2(wgt[r*3+2], R[r],   a0);
            a1 = __hfma2(wgt[r*3+0], L[r+1], a1);
            a1 = __hfma2(wgt[r*3+1], C[r+1], a1);
            a1 = __hfma2(wgt[r*3+2], R[r+1], a1);
        }
        *(__half2*)(out0 + (size_t)w * D_) = __hadd2(a0, C[1]);
        *(__half2*)(out1 + (size_t)w * D_) = __hadd2(a1, C[2]);
        #pragma unroll
        for (int r = 0; r < 4; r++){ L[r] = C[r]; C[r] = R[r]; }
    }
}

// ---------------- 6) logits via wmma: C[token, headpad] = X(16x1024) * U16(1024x16) ----------------
__global__ void __launch_bounds__(256) k_logits_w(){
    int b    = blockIdx.y;
    int warp = threadIdx.x >> 5, lane = threadIdx.x & 31;
    int m0   = (blockIdx.x*8 + warp) * 16;

    wmma::fragment<wmma::matrix_a,16,16,16,__half,wmma::row_major> fa;
    wmma::fragment<wmma::matrix_b,16,16,16,__half,wmma::row_major> fb;
    wmma::fragment<wmma::accumulator,16,16,16,float> fc_;
    wmma::fill_fragment(fc_, 0.f);

    const __half* xr = g_x   + ((size_t)b*N_ + m0) * D_;
    const __half* ur = g_u16 + (size_t)b*D_*16;
    #pragma unroll 4
    for (int k = 0; k < 64; k++){
        wmma::load_matrix_sync(fa, xr + k*16, D_);
        wmma::load_matrix_sync(fb, ur + k*16*16, 16);
        wmma::mma_sync(fc_, fa, fb, fc_);
    }
    __shared__ float sst[8][256];
    wmma::store_matrix_sync(&sst[warp][0], fc_, 16, wmma::mem_row_major);
    __syncwarp();
    #pragma unroll
    for (int e = lane; e < 128; e += 32){
        int tok = e >> 3, h = e & 7;
        g_logits[((size_t)(b*H_ + h))*NTOK + m0 + tok + 1] = sst[warp][tok*16 + h] * 0.03125f;
    }
}

// ---------------- 7) softmax over 4097 (cls inline) + emit fp16 A + init xbar cls term ----------------
__global__ void __launch_bounds__(256) k_softmax(const float* __restrict__ cls){
    int bh = blockIdx.x;
    int b = bh >> 3, h = bh & 7;
    float* lg = g_logits + (size_t)bh * NTOK;
    __shared__ float sred[8];
    __shared__ float sbc;
    int lane = threadIdx.x & 31, warp = threadIdx.x >> 5;

    // cls logit (k=0): dot(u[bh], cls)/32
    {
        const float* u = g_u + (size_t)bh * D_;
        float a = 0.f;
        for (int d = threadIdx.x; d < D_; d += 256) a += u[d] * cls[d];
        a = warp_sum(a);
        if (lane == 0) sred[warp] = a;
        __syncthreads();
        if (threadIdx.x == 0){
            float s = 0.f;
            #pragma unroll
            for (int i = 0; i < 8; i++) s += sred[i];
            lg[0] = s * 0.03125f;
        }
        __syncthreads();
    }

    float mx = -INFINITY;
    for (int k = threadIdx.x; k < NTOK; k += 256) mx = fmaxf(mx, lg[k]);
    #pragma unroll
    for (int o = 16; o; o >>= 1) mx = fmaxf(mx, __shfl_xor_sync(0xffffffffu, mx, o));
    if (lane == 0) sred[warp] = mx;
    __syncthreads();
    if (threadIdx.x == 0){
        float m = sred[0];
        #pragma unroll
        for (int i = 1; i < 8; i++) m = fmaxf(m, sred[i]);
        sbc = m;
    }
    __syncthreads();
    float m = sbc;

    float sum = 0.f;
    for (int k = threadIdx.x; k < NTOK; k += 256){
        float e = expf(lg[k] - m);
        lg[k] = e;
        sum += e;
    }
    sum = warp_sum(sum);
    if (lane == 0) sred[warp] = sum;
    __syncthreads();
    if (threadIdx.x == 0){
        float s = 0.f;
        #pragma unroll
        for (int i = 0; i < 8; i++) s += sred[i];
        sbc = s;
    }
    __syncthreads();
    float inv = 1.f / sbc;
    __half* arow = g_A16 + ((size_t)b*16 + h) * 4096;
    for (int k = threadIdx.x; k < NTOK; k += 256){
        float v = lg[k] * inv;
        lg[k] = v;
        if (k > 0) arow[k-1] = __float2half(v);
    }
    __syncthreads();

    float a0 = lg[0];
    float* xb = g_xbar + ((size_t)b*16 + h) * D_;
    for (int d = threadIdx.x; d < D_; d += 256)
        xb[d] = a0 * cls[d];
}

// ---------------- 8) xbar via wmma: C[headpad, d] += A(16x4096) * X(4096x1024) ----------------
// grid (4 nt-blocks, 8 k-chunks, B); warp handles n-tiles {nt, nt+32}, 32 k-steps; atomicAdd partials.
__global__ void __launch_bounds__(256) k_xbar_w(){
    int b    = blockIdx.z;
    int ks   = blockIdx.y;
    int warp = threadIdx.x >> 5, lane = threadIdx.x & 31;
    int nt0  = blockIdx.x*8 + warp;         // 0..31

    wmma::fragment<wmma::matrix_a,16,16,16,__half,wmma::row_major> fa;
    wmma::fragment<wmma::matrix_b,16,16,16,__half,wmma::row_major> fb0, fb1;
    wmma::fragment<wmma::accumulator,16,16,16,float> acc0, acc1;
    wmma::fill_fragment(acc0, 0.f);
    wmma::fill_fragment(acc1, 0.f);

    const __half* ar = g_A16 + (size_t)b*16*4096 + ks*32*16;
    const __half* xr = g_x   + ((size_t)b*N_ + ks*32*16) * D_;
    for (int k = 0; k < 32; k++){
        wmma::load_matrix_sync(fa, ar + k*16, 4096);
        wmma::load_matrix_sync(fb0, xr + (size_t)k*16*D_ + nt0*16, D_);
        wmma::load_matrix_sync(fb1, xr + (size_t)k*16*D_ + (nt0+32)*16, D_);
        wmma::mma_sync(acc0, fa, fb0, acc0);
        wmma::mma_sync(acc1, fa, fb1, acc1);
    }
    __shared__ float sx[8][512];
    wmma::store_matrix_sync(&sx[warp][0],   acc0, 16, wmma::mem_row_major);
    wmma::store_matrix_sync(&sx[warp][256], acc1, 16, wmma::mem_row_major);
    __syncwarp();
    #pragma unroll
    for (int e = lane; e < 128; e += 32){       // rows 0..7 only
        int r = e >> 4, c = e & 15;
        atomicAdd(&g_xbar[((size_t)b*16 + r)*D_ + nt0*16 + c],      sx[warp][r*16 + c]);
        atomicAdd(&g_xbar[((size_t)b*16 + r)*D_ + (nt0+32)*16 + c], sx[warp][256 + r*16 + c]);
    }
}

// ---------------- 9) O: block per row j ----------------
__global__ void __launch_bounds__(256) k_O(const float* __restrict__ Wv, const float* __restrict__ bv){
    int j = blockIdx.x, t = threadIdx.x, lane = t & 31, wp = t >> 5;
    int h = j >> 7;
    float4 w = __ldg((const float4*)(Wv + (size_t)j * D_) + t);
    float acc[B_];
    #pragma unroll
    for (int b = 0; b < B_; b++){
        float4 v = __ldg((const float4*)(g_xbar + ((size_t)(b*16 + h))*D_) + t);
        acc[b] = w.x*v.x + w.y*v.y + w.z*v.z + w.w*v.w;
    }
    __shared__ float red[8][B_];
    #pragma unroll
    for (int b = 0; b < B_; b++) acc[b] = warp_sum(acc[b]);
    if (lane == 0){
        #pragma unroll
        for (int b = 0; b < B_; b++) red[wp][b] = acc[b];
    }
    __syncthreads();
    if (t < B_){
        float s = 0.f;
        #pragma unroll
        for (int i = 0; i < 8; i++) s += red[i][t];
        g_O[t*D_ + j] = g_Qp[t*D_ + j] + bv[j] + s;
    }
}

// ---------------- 10) O2 = O + relu(O @ Wo^T + bo) ----------------
__global__ void __launch_bounds__(256) k_O2(const float* __restrict__ Wo, const float* __restrict__ bo){
    int j = blockIdx.x, t = threadIdx.x, lane = t & 31, wp = t >> 5;
    float4 w = __ldg((const float4*)(Wo + (size_t)j * D_) + t);
    float acc[B_];
    #pragma unroll
    for (int b = 0; b < B_; b++){
        float4 v = __ldg((const float4*)(g_O + (size_t)b*D_) + t);
        acc[b] = w.x*v.x + w.y*v.y + w.z*v.z + w.w*v.w;
    }
    __shared__ float red[8][B_];
    #pragma unroll
    for (int b = 0; b < B_; b++) acc[b] = warp_sum(acc[b]);
    if (lane == 0){
        #pragma unroll
        for (int b = 0; b < B_; b++) red[wp][b] = acc[b];
    }
    __syncthreads();
    if (t < B_){
        float s = 0.f;
        #pragma unroll
        for (int i = 0; i < 8; i++) s += red[i][t];
        g_O2[t*D_ + j] = g_O[t*D_ + j] + fmaxf(s + bo[j], 0.f);
    }
}

// ---------------- 11) out = O2 @ Wfc^T + bfc  -> (8, 2) ----------------
__global__ void k_fc(const float* __restrict__ Wfc, const float* __restrict__ bfc,
                     float* __restrict__ out){
    int b    = blockIdx.x;
    int c    = threadIdx.x >> 5;
    int lane = threadIdx.x & 31;
    const float4* wr = (const float4*)(Wfc + (size_t)c * D_);
    const float4* op = (const float4*)(g_O2 + (size_t)b * D_);
    float acc = 0.f;
    #pragma unroll
    for (int it = 0; it < 8; it++){
        float4 w = wr[it*32 + lane];
        float4 v = op[it*32 + lane];
        acc += w.x*v.x + w.y*v.y + w.z*v.z + w.w*v.w;
    }
    acc = warp_sum(acc);
    if (lane == 0) out[b*2 + c] = acc + bfc[c];
}

// ---------------- stream/event infra (created in global ctor) ----------------
static cudaStream_t s_aux;
static cudaEvent_t  ev_q, ev_conv;
namespace {
struct _FRMIL_Init {
    _FRMIL_Init(){
        cudaStreamCreateWithFlags(&s_aux, cudaStreamNonBlocking);
        cudaEventCreateWithFlags(&ev_q,    cudaEventDisableTiming);
        cudaEventCreateWithFlags(&ev_conv, cudaEventDisableTiming);
    }
} _frmil_init_;
}

// ---------------- launcher ----------------
extern "C" void kernel_launch(void* const* d_in, const int* in_sizes, int n_in,
                              void* d_out, int out_size){
    const float* inputs = (const float*)d_in[0];
    const float* Wenc   = (const float*)d_in[1];
    // d_in[2] = b_enc : constant shift through sigmoid, irrelevant for argmax
    const float* cls    = (const float*)d_in[3];
    const float* convw  = (const float*)d_in[4];
    const float* convb  = (const float*)d_in[5];
    const float* Wq     = (const float*)d_in[6];
    const float* bq     = (const float*)d_in[7];
    const float* Wk     = (const float*)d_in[8];
    // d_in[9] = bk : constant per (b,h) logit offset -> cancels in softmax
    const float* Wv     = (const float*)d_in[10];
    const float* bv     = (const float*)d_in[11];
    const float* Wo     = (const float*)d_in[12];
    const float* bo     = (const float*)d_in[13];
    const float* Wfc    = (const float*)d_in[14];
    const float* bfc    = (const float*)d_in[15];
    float* out = (float*)d_out;

    k_score<<<B_*N_/8, 256>>>(inputs, Wenc);     // score + argmax + g_u zero + Q copy
    cudaEventRecord(ev_q, 0);

    // aux: conv overlaps qp/u/u16 on main
    cudaStreamWaitEvent(s_aux, ev_q, 0);
    k_conv<<<dim3(16, 4, B_), 256, 0, s_aux>>>(inputs, convw, convb);
    cudaEventRecord(ev_conv, s_aux);

    k_qp  <<<D_, 256>>>(Wq, bq);
    k_u   <<<dim3(16, H_, 4), 256>>>(Wk);
    k_u16 <<<32, 256>>>();

    cudaStreamWaitEvent(0, ev_conv, 0);
    k_logits_w<<<dim3(32, B_), 256>>>();
    k_softmax <<<B_*H_, 256>>>(cls);
    k_xbar_w  <<<dim3(4, 8, B_), 256>>>();
    k_O       <<<D_, 256>>>(Wv, bv);
    k_O2      <<<D_, 256>>>(Wo, bo);
    k_fc      <<<B_, 64>>>(Wfc, bfc, out);
}

// round 11
// speedup vs baseline: 1.3426x; 1.0170x over previous
#include <cuda_runtime.h>
#include <cuda_fp16.h>
#include <mma.h>
#include <math.h>

using namespace nvcuda;

#define B_ 8
#define N_ 4096
#define D_ 1024
#define H_ 8
#define NTOK 4097   // 1 cls + 4096 feat tokens

// ---------------- scratch (static device allocations only) ----------------
__device__ unsigned long long g_best[B_];     // packed (score_key << 32) | ~idx
__device__ int    g_tick[B_];                 // score completion tickets (self-resetting)
__device__ float  g_Q[B_*D_];
__device__ float  g_Qp[B_*D_];
__device__ float  g_u[B_*H_*D_];
__device__ __half g_u16[B_*D_*16];            // u fp16, [b][d][16 head-pad]; heads 8-15 stay 0
__device__ __half g_x[(size_t)B_*N_*D_];      // post relu+conv features, fp16
__device__ float  g_logits[B_*H_*NTOK];
__device__ __half g_A16[(size_t)B_*16*4096];  // softmax weights fp16; rows 8-15 stay 0
__device__ float  g_xbar[B_*16*D_];           // [b][16 head-pad][d]
__device__ float  g_O[B_*D_];

// grid-barrier state (generation counter: replay-safe, never reset)
__device__ int          g_bar_count = 0;
__device__ volatile int g_bar_gen   = 0;

#define TAIL_BLOCKS 256

// Grid barrier: every thread fences its own global stores/atomics before
// arrival; release via generation bump. NOTE: data read after this barrier
// must use PLAIN loads (never __ldg) if it was written within this kernel.
__device__ __forceinline__ void grid_bar(){
    __threadfence();                 // flush THIS thread's global STG/RED
    __syncthreads();                 // all threads of block have fenced
    if (threadIdx.x == 0){
        int gen = g_bar_gen;
        if (atomicAdd(&g_bar_count, 1) == TAIL_BLOCKS - 1){
            atomicExch(&g_bar_count, 0);
            __threadfence();
            g_bar_gen = gen + 1;
        } else {
            while (g_bar_gen == gen) __nanosleep(32);
        }
        __threadfence();
    }
    __syncthreads();
}

__device__ __forceinline__ float warp_sum(float v){
    #pragma unroll
    for (int o = 16; o; o >>= 1) v += __shfl_xor_sync(0xffffffffu, v, o);
    return v;
}

// load float2 (2 channels), relu(v - q) in half2
__device__ __forceinline__ __half2 ld_relu2(const float* p, __half2 q){
    float2 v = *(const float2*)p;
    return __hmax2(__hsub2(__floats2half2_rn(v.x, v.y), q), __float2half2_rn(0.f));
}

// ---------------- 1) score + fused argmax + fused g_u zero + fused Q copy ----------------
__global__ void k_score(const float* __restrict__ inp, const float* __restrict__ wenc){
    int gw   = blockIdx.x*8 + (threadIdx.x >> 5);
    int lane = threadIdx.x & 31;
    int b    = blockIdx.x >> 9;                      // 512 blocks per batch

    if (threadIdx.x < 4)
        ((float4*)g_u)[blockIdx.x*4 + threadIdx.x] = make_float4(0.f,0.f,0.f,0.f);

    const float4* row = (const float4*)(inp + (size_t)gw * D_);
    const float4* wp  = (const float4*)wenc;
    float acc = 0.f;
    #pragma unroll
    for (int j = 0; j < 8; j++){
        float4 x = row[j*32 + lane];
        float4 w = __ldg(&wp[j*32 + lane]);
        acc += x.x*w.x + x.y*w.y + x.z*w.z + x.w*w.w;
    }
    acc = warp_sum(acc);
    __shared__ unsigned long long sbest[8];
    if (lane == 0){
        unsigned int fb  = __float_as_uint(acc);
        unsigned int key = (fb & 0x80000000u) ? ~fb : (fb | 0x80000000u);
        unsigned int n   = (unsigned int)(gw & (N_-1));
        sbest[threadIdx.x >> 5] = ((unsigned long long)key << 32) | (unsigned long long)(~n);
    }
    __syncthreads();
    __shared__ int slast;
    if (threadIdx.x == 0){
        unsigned long long m = sbest[0];
        #pragma unroll
        for (int i = 1; i < 8; i++) m = (sbest[i] > m) ? sbest[i] : m;
        atomicMax(&g_best[b], m);
        __threadfence();
        slast = (atomicAdd(&g_tick[b], 1) == 511);
    }
    __syncthreads();
    if (slast){
        __threadfence();
        unsigned int n = (~(unsigned int)(g_best[b] & 0xffffffffull)) & (N_-1);
        const float4* src = (const float4*)(inp + ((size_t)b*N_ + n) * D_);
        float4* dq = (float4*)(g_Q + b*D_);
        dq[threadIdx.x] = src[threadIdx.x];
        if (threadIdx.x == 0) g_tick[b] = 0;
    }
}

// ---------------- 2) Qp: block per output row j ----------------
__global__ void __launch_bounds__(256) k_qp(const float* __restrict__ Wq, const float* __restrict__ bq){
    int j = blockIdx.x, t = threadIdx.x, lane = t & 31, wp = t >> 5;
    float4 w = __ldg((const float4*)(Wq + (size_t)j * D_) + t);
    float acc[B_];
    #pragma unroll
    for (int b = 0; b < B_; b++){
        float4 q = __ldg((const float4*)(g_Q + b*D_) + t);
        acc[b] = w.x*q.x + w.y*q.y + w.z*q.z + w.w*q.w;
    }
    __shared__ float red[8][B_];
    #pragma unroll
    for (int b = 0; b < B_; b++) acc[b] = warp_sum(acc[b]);
    if (lane == 0){
        #pragma unroll
        for (int b = 0; b < B_; b++) red[wp][b] = acc[b];
    }
    __syncthreads();
    if (t < B_){
        float s = 0.f;
        #pragma unroll
        for (int i = 0; i < 8; i++) s += red[i][t];
        g_Qp[t*D_ + j] = s + bq[j];
    }
}

// ---------------- 3) u[b,h,i] += partial (grid (16,H,4), atomic accumulate) ----------------
__global__ void __launch_bounds__(256) k_u(const float* __restrict__ Wk){
    int h  = blockIdx.y, jc = blockIdx.z;
    int il = threadIdx.x & 63;
    int js = threadIdx.x >> 6;

    __shared__ float qp[B_][32];
    { int t = threadIdx.x;
      qp[t >> 5][t & 31] = g_Qp[(t >> 5)*D_ + h*128 + jc*32 + (t & 31)]; }
    __syncthreads();

    int i = blockIdx.x*64 + il;
    const float* wkp = Wk + (size_t)(h*128 + jc*32 + js*8) * D_ + i;
    float acc[B_];
    #pragma unroll
    for (int b = 0; b < B_; b++) acc[b] = 0.f;
    #pragma unroll
    for (int j = 0; j < 8; j++){
        float w = wkp[(size_t)j * D_];
        #pragma unroll
        for (int b = 0; b < B_; b++) acc[b] += qp[b][js*8 + j] * w;
    }

    __shared__ float part[4][64][B_];
    #pragma unroll
    for (int b = 0; b < B_; b++) part[js][il][b] = acc[b];
    __syncthreads();

    for (int idx = threadIdx.x; idx < 64*B_; idx += 256){
        int ii = idx >> 3, b = idx & 7;
        float s = part[0][ii][b] + part[1][ii][b] + part[2][ii][b] + part[3][ii][b];
        atomicAdd(&g_u[((size_t)(b*H_ + h))*D_ + blockIdx.x*64 + ii], s);
    }
}

// ---------------- 4) u -> fp16 transpose [b][d][16]; heads 8..15 remain 0 ----------------
__global__ void k_u16(){
    int idx = blockIdx.x*256 + threadIdx.x;
    int b = idx >> 10, d = idx & 1023;
    __half h8[8];
    #pragma unroll
    for (int h = 0; h < 8; h++)
        h8[h] = __float2half(g_u[(((size_t)(b*H_ + h)) << 10) | d]);
    __half* dst = g_u16 + (size_t)idx * 16;
    *(uint4*)dst = *(uint4*)h8;
    *(uint4*)(dst + 8) = make_uint4(0,0,0,0);
}

// ---------------- 5) relu + depthwise 3x3 conv + residual -> g_x (HFMA2, 2 rows x 2 ch) ----------------
__global__ void __launch_bounds__(256, 4) k_conv(const float* __restrict__ inp,
                                                 const float* __restrict__ convw,
                                                 const float* __restrict__ convb){
    int b  = blockIdx.z;
    int cg = threadIdx.x & 31;
    int tr = threadIdx.x >> 5;
    int c0 = blockIdx.x*64 + cg*2;
    int h0 = blockIdx.y*16 + tr*2;

    const float* base = inp + (size_t)b*N_*D_ + c0;
    float2 qf = *(const float2*)(g_Q + b*D_ + c0);
    __half2 q  = __floats2half2_rn(qf.x, qf.y);
    float2 cf = *(const float2*)(convb + c0);
    __half2 cb = __floats2half2_rn(cf.x, cf.y);

    __half2 wgt[9];
    #pragma unroll
    for (int k = 0; k < 9; k++)
        wgt[k] = __floats2half2_rn(convw[(c0+0)*9 + k], convw[(c0+1)*9 + k]);

    bool vld[4];
    const float* rp[4];
    #pragma unroll
    for (int r = 0; r < 4; r++){
        int hh = h0 - 1 + r;
        vld[r] = (hh >= 0) && (hh < 64);
        int hc = hh < 0 ? 0 : (hh > 63 ? 63 : hh);
        rp[r] = base + (size_t)(hc*64) * D_;
    }

    __half2 Z = __float2half2_rn(0.f);
    __half2 L[4], C[4], R[4];
    #pragma unroll
    for (int r = 0; r < 4; r++){
        L[r] = Z;
        C[r] = vld[r] ? ld_relu2(rp[r], q) : Z;
    }

    __half* out0 = g_x + ((size_t)b*N_ + h0*64) * D_ + c0;
    __half* out1 = out0 + (size_t)64 * D_;
    #pragma unroll 4
    for (int w = 0; w < 64; w++){
        #pragma unroll
        for (int r = 0; r < 4; r++)
            R[r] = (w < 63 && vld[r]) ? ld_relu2(rp[r] + (size_t)(w+1) * D_, q) : Z;

        __half2 a0 = cb, a1 = cb;
        #pragma unroll
        for (int r = 0; r < 3; r++){
            a0 = __hfma2(wgt[r*3+0], L[r],   a0);
            a0 = __hfma2(wgt[r*3+1], C[r],   a0);
            a0 = __hfma2(wgt[r*3+2], R[r],   a0);
            a1 = __hfma2(wgt[r*3+0], L[r+1], a1);
            a1 = __hfma2(wgt[r*3+1], C[r+1], a1);
            a1 = __hfma2(wgt[r*3+2], R[r+1], a1);
        }
        *(__half2*)(out0 + (size_t)w * D_) = __hadd2(a0, C[1]);
        *(__half2*)(out1 + (size_t)w * D_) = __hadd2(a1, C[2]);
        #pragma unroll
        for (int r = 0; r < 4; r++){ L[r] = C[r]; C[r] = R[r]; }
    }
}

// ---------------- 6) TAIL megakernel: logits -> softmax -> xbar -> O -> O2+fc ----------------
// 256 blocks x 256 threads; launch_bounds(256,2) forces co-residency.
// CRITICAL: buffers written within this kernel (g_xbar, g_O, g_logits, g_A16)
// are read ONLY via plain loads — __ldg is reserved for true kernel-constants.
__global__ void __launch_bounds__(256, 2) k_tail(const float* __restrict__ cls,
                                                 const float* __restrict__ Wv, const float* __restrict__ bv,
                                                 const float* __restrict__ Wo, const float* __restrict__ bo,
                                                 const float* __restrict__ Wfc, const float* __restrict__ bfc,
                                                 float* __restrict__ out){
    int t = threadIdx.x, lane = t & 31, warp = t >> 5;
    __shared__ float smem_buf[8*512];   // 16KB, reused across phases
    __shared__ float sred[8];
    __shared__ float sbc;

    // ===== Phase L: logits via wmma =====
    {
        int b  = blockIdx.x >> 5;
        int m0 = ((blockIdx.x & 31)*8 + warp) * 16;

        wmma::fragment<wmma::matrix_a,16,16,16,__half,wmma::row_major> fa;
        wmma::fragment<wmma::matrix_b,16,16,16,__half,wmma::row_major> fb;
        wmma::fragment<wmma::accumulator,16,16,16,float> fc_;
        wmma::fill_fragment(fc_, 0.f);

        const __half* xr = g_x   + ((size_t)b*N_ + m0) * D_;
        const __half* ur = g_u16 + (size_t)b*D_*16;
        #pragma unroll 4
        for (int k = 0; k < 64; k++){
            wmma::load_matrix_sync(fa, xr + k*16, D_);
            wmma::load_matrix_sync(fb, ur + k*16*16, 16);
            wmma::mma_sync(fc_, fa, fb, fc_);
        }
        float* sst = smem_buf + warp*256;
        wmma::store_matrix_sync(sst, fc_, 16, wmma::mem_row_major);
        __syncwarp();
        #pragma unroll
        for (int e = lane; e < 128; e += 32){
            int tok = e >> 3, h = e & 7;
            g_logits[((size_t)(b*H_ + h))*NTOK + m0 + tok + 1] = sst[tok*16 + h] * 0.03125f;
        }
    }
    grid_bar();

    // ===== Phase S: softmax (blocks 0..63, one per (b,h)) + A16 emit + xbar cls init =====
    if (blockIdx.x < 64){
        int bh = blockIdx.x;
        int b = bh >> 3, h = bh & 7;
        float* lg = g_logits + (size_t)bh * NTOK;

        // cls logit (k=0)
        {
            const float* u = g_u + (size_t)bh * D_;
            float a = 0.f;
            for (int d = t; d < D_; d += 256) a += u[d] * cls[d];
            a = warp_sum(a);
            if (lane == 0) sred[warp] = a;
            __syncthreads();
            if (t == 0){
                float s = 0.f;
                #pragma unroll
                for (int i = 0; i < 8; i++) s += sred[i];
                lg[0] = s * 0.03125f;
            }
            __syncthreads();
        }

        float mx = -INFINITY;
        for (int k = t; k < NTOK; k += 256) mx = fmaxf(mx, lg[k]);
        #pragma unroll
        for (int o = 16; o; o >>= 1) mx = fmaxf(mx, __shfl_xor_sync(0xffffffffu, mx, o));
        if (lane == 0) sred[warp] = mx;
        __syncthreads();
        if (t == 0){
            float m = sred[0];
            #pragma unroll
            for (int i = 1; i < 8; i++) m = fmaxf(m, sred[i]);
            sbc = m;
        }
        __syncthreads();
        float m = sbc;

        float sum = 0.f;
        for (int k = t; k < NTOK; k += 256){
            float e = expf(lg[k] - m);
            lg[k] = e;
            sum += e;
        }
        sum = warp_sum(sum);
        if (lane == 0) sred[warp] = sum;
        __syncthreads();
        if (t == 0){
            float s = 0.f;
            #pragma unroll
            for (int i = 0; i < 8; i++) s += sred[i];
            sbc = s;
        }
        __syncthreads();
        float inv = 1.f / sbc;
        __half* arow = g_A16 + ((size_t)b*16 + h) * 4096;
        for (int k = t; k < NTOK; k += 256){
            float v = lg[k] * inv;
            lg[k] = v;
            if (k > 0) arow[k-1] = __float2half(v);
        }
        __syncthreads();

        float a0 = lg[0];
        float* xb = g_xbar + ((size_t)b*16 + h) * D_;
        for (int d = t; d < D_; d += 256)
            xb[d] = a0 * cls[d];
    }
    grid_bar();

    // ===== Phase X: xbar via wmma, atomic accumulate =====
    {
        int b   = blockIdx.x >> 5;
        int s5  = blockIdx.x & 31;
        int ks  = s5 >> 2;                 // 0..7
        int nt0 = (s5 & 3)*8 + warp;       // 0..31

        wmma::fragment<wmma::matrix_a,16,16,16,__half,wmma::row_major> fa;
        wmma::fragment<wmma::matrix_b,16,16,16,__half,wmma::row_major> fb0, fb1;
        wmma::fragment<wmma::accumulator,16,16,16,float> acc0, acc1;
        wmma::fill_fragment(acc0, 0.f);
        wmma::fill_fragment(acc1, 0.f);

        const __half* ar = g_A16 + (size_t)b*16*4096 + ks*32*16;
        const __half* xr = g_x   + ((size_t)b*N_ + ks*32*16) * D_;
        for (int k = 0; k < 32; k++){
            wmma::load_matrix_sync(fa, ar + k*16, 4096);
            wmma::load_matrix_sync(fb0, xr + (size_t)k*16*D_ + nt0*16, D_);
            wmma::load_matrix_sync(fb1, xr + (size_t)k*16*D_ + (nt0+32)*16, D_);
            wmma::mma_sync(acc0, fa, fb0, acc0);
            wmma::mma_sync(acc1, fa, fb1, acc1);
        }
        float* sx = smem_buf + warp*512;
        wmma::store_matrix_sync(sx,       acc0, 16, wmma::mem_row_major);
        wmma::store_matrix_sync(sx + 256, acc1, 16, wmma::mem_row_major);
        __syncwarp();
        #pragma unroll
        for (int e = lane; e < 128; e += 32){       // rows 0..7 only
            int r = e >> 4, c = e & 15;
            atomicAdd(&g_xbar[((size_t)b*16 + r)*D_ + nt0*16 + c],      sx[r*16 + c]);
            atomicAdd(&g_xbar[((size_t)b*16 + r)*D_ + (nt0+32)*16 + c], sx[256 + r*16 + c]);
        }
    }
    grid_bar();

    // ===== Phase O: O[b,j] = Qp + Wv[j].xbar + bv ; 4 rows per block =====
    // g_xbar written THIS kernel -> PLAIN loads only.
    {
        if (blockIdx.x == 0 && t < 16) out[t] = bfc[t & 1];
        float (*red)[B_] = (float(*)[B_])smem_buf;
        #pragma unroll
        for (int r = 0; r < 4; r++){
            int j = blockIdx.x*4 + r;
            int h = j >> 7;
            float4 w = __ldg((const float4*)(Wv + (size_t)j * D_) + t);
            float acc[B_];
            #pragma unroll
            for (int b = 0; b < B_; b++){
                float4 v = *((const float4*)(g_xbar + ((size_t)(b*16 + h))*D_) + t);  // plain load
                acc[b] = w.x*v.x + w.y*v.y + w.z*v.z + w.w*v.w;
            }
            #pragma unroll
            for (int b = 0; b < B_; b++) acc[b] = warp_sum(acc[b]);
            if (lane == 0){
                #pragma unroll
                for (int b = 0; b < B_; b++) red[warp][b] = acc[b];
            }
            __syncthreads();
            if (t < B_){
                float s = 0.f;
                #pragma unroll
                for (int i = 0; i < 8; i++) s += red[i][t];
                g_O[t*D_ + j] = g_Qp[t*D_ + j] + bv[j] + s;
            }
            __syncthreads();
        }
    }
    grid_bar();

    // ===== Phase F: out[b,c] += (O[b,j] + relu(Wo[j].O[b]+bo[j])) * Wfc[c,j] =====
    // g_O written THIS kernel -> PLAIN loads only.
    {
        float (*red)[B_] = (float(*)[B_])smem_buf;
        float acc0 = 0.f, acc1 = 0.f;   // per-thread (t<8): b = t
        #pragma unroll
        for (int r = 0; r < 4; r++){
            int j = blockIdx.x*4 + r;
            float4 w = __ldg((const float4*)(Wo + (size_t)j * D_) + t);
            float acc[B_];
            #pragma unroll
            for (int b = 0; b < B_; b++){
                float4 v = *((const float4*)(g_O + (size_t)b*D_) + t);   // plain load
                acc[b] = w.x*v.x + w.y*v.y + w.z*v.z + w.w*v.w;
            }
            #pragma unroll
            for (int b = 0; b < B_; b++) acc[b] = warp_sum(acc[b]);
            if (lane == 0){
                #pragma unroll
                for (int b = 0; b < B_; b++) red[warp][b] = acc[b];
            }
            __syncthreads();
            if (t < B_){
                float s = 0.f;
                #pragma unroll
                for (int i = 0; i < 8; i++) s += red[i][t];
                float o2 = g_O[t*D_ + j] + fmaxf(s + bo[j], 0.f);
                acc0 += o2 * Wfc[j];
                acc1 += o2 * Wfc[D_ + j];
            }
            __syncthreads();
        }
        if (t < B_){
            atomicAdd(&out[t*2 + 0], acc0);
            atomicAdd(&out[t*2 + 1], acc1);
        }
    }
}

// ---------------- stream/event infra (created in global ctor) ----------------
static cudaStream_t s_aux;
static cudaEvent_t  ev_q, ev_conv;
namespace {
struct _FRMIL_Init {
    _FRMIL_Init(){
        cudaStreamCreateWithFlags(&s_aux, cudaStreamNonBlocking);
        cudaEventCreateWithFlags(&ev_q,    cudaEventDisableTiming);
        cudaEventCreateWithFlags(&ev_conv, cudaEventDisableTiming);
    }
} _frmil_init_;
}

// ---------------- launcher ----------------
extern "C" void kernel_launch(void* const* d_in, const int* in_sizes, int n_in,
                              void* d_out, int out_size){
    const float* inputs = (const float*)d_in[0];
    const float* Wenc   = (const float*)d_in[1];
    // d_in[2] = b_enc : constant shift through sigmoid, irrelevant for argmax
    const float* cls    = (const float*)d_in[3];
    const float* convw  = (const float*)d_in[4];
    const float* convb  = (const float*)d_in[5];
    const float* Wq     = (const float*)d_in[6];
    const float* bq     = (const float*)d_in[7];
    const float* Wk     = (const float*)d_in[8];
    // d_in[9] = bk : constant per (b,h) logit offset -> cancels in softmax
    const float* Wv     = (const float*)d_in[10];
    const float* bv     = (const float*)d_in[11];
    const float* Wo     = (const float*)d_in[12];
    const float* bo     = (const float*)d_in[13];
    const float* Wfc    = (const float*)d_in[14];
    const float* bfc    = (const float*)d_in[15];
    float* out = (float*)d_out;

    k_score<<<B_*N_/8, 256>>>(inputs, Wenc);     // score + argmax + g_u zero + Q copy
    cudaEventRecord(ev_q, 0);

    // aux: conv overlaps qp/u/u16 on main
    cudaStreamWaitEvent(s_aux, ev_q, 0);
    k_conv<<<dim3(16, 4, B_), 256, 0, s_aux>>>(inputs, convw, convb);
    cudaEventRecord(ev_conv, s_aux);

    k_qp  <<<D_, 256>>>(Wq, bq);
    k_u   <<<dim3(16, H_, 4), 256>>>(Wk);
    k_u16 <<<32, 256>>>();

    cudaStreamWaitEvent(0, ev_conv, 0);
    k_tail<<<TAIL_BLOCKS, 256>>>(cls, Wv, bv, Wo, bo, Wfc, bfc, out);
}